// round 1
// baseline (speedup 1.0000x reference)
#include <cuda_runtime.h>
#include <cstddef>

// Problem dims
#define BATCH 2
#define TSEQ  2048
#define EDIM  1024
#define FDIM  4096
#define NHEAD 16
#define HDIM  64
#define MTOK  (BATCH*TSEQ)   // 4096 rows

// ---------------- scratch (device globals: allocation-free) ----------------
__device__ float g_xn [MTOK*EDIM];
__device__ float g_q  [MTOK*EDIM];
__device__ float g_k  [MTOK*EDIM];
__device__ float g_v  [MTOK*EDIM];
__device__ float g_att[MTOK*EDIM];
__device__ float g_x1 [MTOK*EDIM];
__device__ float g_h  [MTOK*EDIM];
__device__ float g_hid[MTOK*FDIM];

// ---------------- fused LayerNorm: one block per row (E=1024) ----------------
__global__ __launch_bounds__(256)
void ln_kernel(const float* __restrict__ x, const float* __restrict__ g,
               const float* __restrict__ b, float* __restrict__ y)
{
    __shared__ float red[8];
    int row = blockIdx.x;
    int t = threadIdx.x;
    const float4* xr = (const float4*)(x + (size_t)row * EDIM);
    float4 v = xr[t];
    float s = v.x + v.y + v.z + v.w;
    #pragma unroll
    for (int o = 16; o > 0; o >>= 1) s += __shfl_xor_sync(0xffffffffu, s, o);
    if ((t & 31) == 0) red[t >> 5] = s;
    __syncthreads();
    float tot = 0.f;
    #pragma unroll
    for (int i = 0; i < 8; i++) tot += red[i];
    float mean = tot * (1.0f / EDIM);
    float dx = v.x - mean, dy = v.y - mean, dz = v.z - mean, dw = v.w - mean;
    float s2 = dx*dx + dy*dy + dz*dz + dw*dw;
    __syncthreads();
    #pragma unroll
    for (int o = 16; o > 0; o >>= 1) s2 += __shfl_xor_sync(0xffffffffu, s2, o);
    if ((t & 31) == 0) red[t >> 5] = s2;
    __syncthreads();
    float tot2 = 0.f;
    #pragma unroll
    for (int i = 0; i < 8; i++) tot2 += red[i];
    float r = rsqrtf(tot2 * (1.0f / EDIM) + 1e-5f);
    float4 g4 = ((const float4*)g)[t];
    float4 b4 = ((const float4*)b)[t];
    float4 o4;
    o4.x = dx * r * g4.x + b4.x;
    o4.y = dy * r * g4.y + b4.y;
    o4.z = dz * r * g4.z + b4.z;
    o4.w = dw * r * g4.w + b4.w;
    ((float4*)(y + (size_t)row * EDIM))[t] = o4;
}

// ---------------- tiled fp32 SGEMM: C = A[M,K] @ W[K,N] (+bias)(+relu)(+resid) --
// BM=BN=128, BK=8, 256 threads, 8x8 per-thread microtile. All dims divisible.
__global__ __launch_bounds__(256)
void sgemm_kernel(const float* __restrict__ A, const float* __restrict__ W,
                  float* __restrict__ C, const float* __restrict__ bias,
                  const float* __restrict__ resid,
                  int M, int N, int K, int relu)
{
    const int BM = 128, BN = 128, BK = 8, TM = 8, TN = 8;
    __shared__ float As[BK][BM];
    __shared__ float Bs[BK][BN];
    int tid = threadIdx.x;
    int bn = blockIdx.x, bm = blockIdx.y;
    const float* Ab = A + (size_t)bm * BM * K;
    const float* Wb = W + (size_t)bn * BN;
    int arow = tid >> 1;          // 0..127
    int acol = (tid & 1) << 2;    // 0 or 4
    int brow = tid >> 5;          // 0..7
    int bcol = (tid & 31) << 2;   // 0..124
    int trow = (tid >> 4) * TM;
    int tcol = (tid & 15) * TN;

    float acc[TM][TN];
    #pragma unroll
    for (int i = 0; i < TM; i++)
        #pragma unroll
        for (int j = 0; j < TN; j++) acc[i][j] = 0.f;

    for (int k0 = 0; k0 < K; k0 += BK) {
        float4 a4 = *(const float4*)(Ab + (size_t)arow * K + k0 + acol);
        As[acol+0][arow] = a4.x;
        As[acol+1][arow] = a4.y;
        As[acol+2][arow] = a4.z;
        As[acol+3][arow] = a4.w;
        float4 b4 = *(const float4*)(Wb + (size_t)(k0 + brow) * N + bcol);
        *(float4*)&Bs[brow][bcol] = b4;
        __syncthreads();
        #pragma unroll
        for (int kk = 0; kk < BK; kk++) {
            float ra[TM], rb[TN];
            *(float4*)&ra[0] = *(const float4*)&As[kk][trow];
            *(float4*)&ra[4] = *(const float4*)&As[kk][trow + 4];
            *(float4*)&rb[0] = *(const float4*)&Bs[kk][tcol];
            *(float4*)&rb[4] = *(const float4*)&Bs[kk][tcol + 4];
            #pragma unroll
            for (int i = 0; i < TM; i++)
                #pragma unroll
                for (int j = 0; j < TN; j++)
                    acc[i][j] += ra[i] * rb[j];
        }
        __syncthreads();
    }

    #pragma unroll
    for (int i = 0; i < TM; i++) {
        size_t roff = (size_t)(bm * BM + trow + i) * N + bn * BN;
        #pragma unroll
        for (int j = 0; j < TN; j += 4) {
            float4 o;
            o.x = acc[i][j];   o.y = acc[i][j+1];
            o.z = acc[i][j+2]; o.w = acc[i][j+3];
            if (bias) {
                float4 bb = *(const float4*)(bias + bn * BN + tcol + j);
                o.x += bb.x; o.y += bb.y; o.z += bb.z; o.w += bb.w;
            }
            if (relu) {
                o.x = fmaxf(o.x, 0.f); o.y = fmaxf(o.y, 0.f);
                o.z = fmaxf(o.z, 0.f); o.w = fmaxf(o.w, 0.f);
            }
            if (resid) {
                float4 rr = *(const float4*)(resid + roff + tcol + j);
                o.x += rr.x; o.y += rr.y; o.z += rr.z; o.w += rr.w;
            }
            *(float4*)(C + roff + tcol + j) = o;
        }
    }
}

// ---------------- causal flash attention, fp32 -------------------------------
// Block: 64 queries of one (b,h). 256 threads: 4 threads per query row
// (c = tid&3 owns 16 keys of S and 16 d-columns of O). Online softmax per row
// via shfl within the 4-lane group; P broadcast via __shfl_sync(width=4).
__global__ __launch_bounds__(256)
void attn_kernel(const float* __restrict__ Q, const float* __restrict__ K,
                 const float* __restrict__ V, float* __restrict__ O)
{
    __shared__ float Ks[64][64];
    __shared__ float Vs[64][64];
    int tid = threadIdx.x;
    int qr = tid >> 2;
    int c  = tid & 3;
    int qt = blockIdx.x;
    int h  = blockIdx.y;
    int b  = blockIdx.z;
    int tq = qt * 64 + qr;
    size_t qoff = ((size_t)(b * TSEQ + tq)) * EDIM + h * HDIM;

    float qreg[64];
    #pragma unroll
    for (int d = 0; d < 64; d += 4) {
        float4 t4 = *(const float4*)(Q + qoff + d);
        qreg[d] = t4.x; qreg[d+1] = t4.y; qreg[d+2] = t4.z; qreg[d+3] = t4.w;
    }

    float m = -1e30f, l = 0.f;
    float o[16];
    #pragma unroll
    for (int i = 0; i < 16; i++) o[i] = 0.f;

    int ntiles = qt + 1;   // causal: only tiles up to the diagonal
    for (int kt = 0; kt < ntiles; kt++) {
        int kbase = kt * 64;
        __syncthreads();
        #pragma unroll
        for (int it = 0; it < 4; it++) {
            int idx = tid + it * 256;            // 0..1023
            int j  = idx >> 4;
            int d4 = (idx & 15) << 2;
            size_t goff = ((size_t)(b * TSEQ + kbase + j)) * EDIM + h * HDIM + d4;
            *(float4*)&Ks[j][d4] = *(const float4*)(K + goff);
            *(float4*)&Vs[j][d4] = *(const float4*)(V + goff);
        }
        __syncthreads();

        float sreg[16];
        #pragma unroll
        for (int jj = 0; jj < 16; jj++) {
            int j = c * 16 + jj;
            float s = 0.f;
            #pragma unroll
            for (int d = 0; d < 64; d += 4) {
                float4 k4 = *(const float4*)&Ks[j][d];
                s += qreg[d]   * k4.x + qreg[d+1] * k4.y
                   + qreg[d+2] * k4.z + qreg[d+3] * k4.w;
            }
            s *= 0.125f;                 // 1/sqrt(64)
            if (kbase + j > tq) s = -1e30f;
            sreg[jj] = s;
        }

        float tm = sreg[0];
        #pragma unroll
        for (int jj = 1; jj < 16; jj++) tm = fmaxf(tm, sreg[jj]);
        tm = fmaxf(tm, __shfl_xor_sync(0xffffffffu, tm, 1));
        tm = fmaxf(tm, __shfl_xor_sync(0xffffffffu, tm, 2));
        float mn = fmaxf(m, tm);
        float corr = __expf(m - mn);
        float ls = 0.f;
        #pragma unroll
        for (int jj = 0; jj < 16; jj++) { sreg[jj] = __expf(sreg[jj] - mn); ls += sreg[jj]; }
        ls += __shfl_xor_sync(0xffffffffu, ls, 1);
        ls += __shfl_xor_sync(0xffffffffu, ls, 2);
        l = l * corr + ls;
        m = mn;
        #pragma unroll
        for (int i = 0; i < 16; i++) o[i] *= corr;

        // O += P @ V ; broadcast p across the 4-lane row group via shfl
        #pragma unroll
        for (int cs = 0; cs < 4; cs++) {
            #pragma unroll
            for (int jj = 0; jj < 16; jj++) {
                float pv = __shfl_sync(0xffffffffu, sreg[jj], cs, 4);
                const float* vrow = &Vs[cs * 16 + jj][c * 16];
                #pragma unroll
                for (int i4 = 0; i4 < 16; i4 += 4) {
                    float4 v4 = *(const float4*)(vrow + i4);
                    o[i4]   += pv * v4.x;
                    o[i4+1] += pv * v4.y;
                    o[i4+2] += pv * v4.z;
                    o[i4+3] += pv * v4.w;
                }
            }
        }
    }

    float inv = 1.f / l;
    size_t ooff = qoff + c * 16;
    #pragma unroll
    for (int i4 = 0; i4 < 16; i4 += 4) {
        float4 t4;
        t4.x = o[i4] * inv;   t4.y = o[i4+1] * inv;
        t4.z = o[i4+2] * inv; t4.w = o[i4+3] * inv;
        *(float4*)(O + ooff + i4) = t4;
    }
}

// ---------------- launch -----------------------------------------------------
extern "C" void kernel_launch(void* const* d_in, const int* in_sizes, int n_in,
                              void* d_out, int out_size)
{
    const float* x    = (const float*)d_in[0];
    const float* ln1g = (const float*)d_in[1];
    const float* ln1b = (const float*)d_in[2];
    const float* Wq   = (const float*)d_in[3];
    const float* Wk   = (const float*)d_in[4];
    const float* Wv   = (const float*)d_in[5];
    const float* Wo   = (const float*)d_in[6];
    const float* bo   = (const float*)d_in[7];
    const float* ln2g = (const float*)d_in[8];
    const float* ln2b = (const float*)d_in[9];
    const float* W1   = (const float*)d_in[10];
    const float* b1   = (const float*)d_in[11];
    const float* W2   = (const float*)d_in[12];
    const float* b2   = (const float*)d_in[13];
    float* out = (float*)d_out;

    float *xn, *q, *k, *v, *att, *x1, *h, *hid;
    cudaGetSymbolAddress((void**)&xn,  g_xn);
    cudaGetSymbolAddress((void**)&q,   g_q);
    cudaGetSymbolAddress((void**)&k,   g_k);
    cudaGetSymbolAddress((void**)&v,   g_v);
    cudaGetSymbolAddress((void**)&att, g_att);
    cudaGetSymbolAddress((void**)&x1,  g_x1);
    cudaGetSymbolAddress((void**)&h,   g_h);
    cudaGetSymbolAddress((void**)&hid, g_hid);

    // 1. xn = LN1(x)
    ln_kernel<<<MTOK, 256>>>(x, ln1g, ln1b, xn);

    // 2. Q,K,V = xn @ W{q,k,v}
    dim3 gE(EDIM / 128, MTOK / 128);
    sgemm_kernel<<<gE, 256>>>(xn, Wq, q, nullptr, nullptr, MTOK, EDIM, EDIM, 0);
    sgemm_kernel<<<gE, 256>>>(xn, Wk, k, nullptr, nullptr, MTOK, EDIM, EDIM, 0);
    sgemm_kernel<<<gE, 256>>>(xn, Wv, v, nullptr, nullptr, MTOK, EDIM, EDIM, 0);

    // 3. causal MHA
    attn_kernel<<<dim3(TSEQ / 64, NHEAD, BATCH), 256>>>(q, k, v, att);

    // 4. x1 = att @ Wo + bo + x
    sgemm_kernel<<<gE, 256>>>(att, Wo, x1, bo, x, MTOK, EDIM, EDIM, 0);

    // 5. h = LN2(x1)
    ln_kernel<<<MTOK, 256>>>(x1, ln2g, ln2b, h);

    // 6. hid = relu(h @ W1 + b1)
    dim3 gF(FDIM / 128, MTOK / 128);
    sgemm_kernel<<<gF, 256>>>(h, W1, hid, b1, nullptr, MTOK, FDIM, EDIM, 1);

    // 7. out = hid @ W2 + b2 + x1
    sgemm_kernel<<<gE, 256>>>(hid, W2, out, b2, x1, MTOK, EDIM, FDIM, 0);
}

// round 3
// speedup vs baseline: 1.5212x; 1.5212x over previous
#include <cuda_runtime.h>
#include <cuda_bf16.h>
#include <cstdint>
#include <cstddef>

// Problem dims
#define BATCH 2
#define TSEQ  2048
#define EDIM  1024
#define FDIM  4096
#define NHEAD 16
#define HDIM  64
#define MTOK  (BATCH*TSEQ)   // 4096 rows

// ---------------- scratch (device globals: allocation-free) ----------------
__device__ float g_xn [MTOK*EDIM];
__device__ float g_q  [MTOK*EDIM];
__device__ float g_k  [MTOK*EDIM];
__device__ float g_v  [MTOK*EDIM];
__device__ float g_att[MTOK*EDIM];
__device__ float g_x1 [MTOK*EDIM];
__device__ float g_h  [MTOK*EDIM];
__device__ float g_hid[MTOK*FDIM];
// bf16 split scratch
__device__ __nv_bfloat16 g_ah [MTOK*FDIM];
__device__ __nv_bfloat16 g_al [MTOK*FDIM];
__device__ __nv_bfloat16 g_wqh[EDIM*EDIM], g_wql[EDIM*EDIM];
__device__ __nv_bfloat16 g_wkh[EDIM*EDIM], g_wkl[EDIM*EDIM];
__device__ __nv_bfloat16 g_wvh[EDIM*EDIM], g_wvl[EDIM*EDIM];
__device__ __nv_bfloat16 g_woh[EDIM*EDIM], g_wol[EDIM*EDIM];
__device__ __nv_bfloat16 g_w1h[FDIM*EDIM], g_w1l[FDIM*EDIM];
__device__ __nv_bfloat16 g_w2h[EDIM*FDIM], g_w2l[EDIM*FDIM];

// ---------------- PTX helpers (sm_80-compatible only) ----------------
__device__ __forceinline__ uint32_t smem_u32(const void* p) {
    uint32_t a;
    asm("{ .reg .u64 t; cvta.to.shared.u64 t, %1; cvt.u32.u64 %0, t; }" : "=r"(a) : "l"(p));
    return a;
}
#define SWZ128(o) ((o) ^ ((((uint32_t)(o)) >> 3) & 0x70u))

#define CP_ASYNC16(dst, src) \
    asm volatile("cp.async.cg.shared.global [%0], [%1], 16;" :: "r"(dst), "l"(src) : "memory")
#define CP_COMMIT()  asm volatile("cp.async.commit_group;" ::: "memory")
#define CP_WAIT(n)   asm volatile("cp.async.wait_group %0;" :: "n"(n) : "memory")

__device__ __forceinline__ void ldsm_x4(uint32_t* r, uint32_t addr) {
    asm volatile("ldmatrix.sync.aligned.m8n8.x4.shared.b16 {%0,%1,%2,%3}, [%4];"
                 : "=r"(r[0]), "=r"(r[1]), "=r"(r[2]), "=r"(r[3]) : "r"(addr));
}
__device__ __forceinline__ void ldsm_x2(uint32_t* r, uint32_t addr) {
    asm volatile("ldmatrix.sync.aligned.m8n8.x2.shared.b16 {%0,%1}, [%2];"
                 : "=r"(r[0]), "=r"(r[1]) : "r"(addr));
}
__device__ __forceinline__ void mma16816(float* c, const uint32_t* a, const uint32_t* b) {
    asm volatile("mma.sync.aligned.m16n8k16.row.col.f32.bf16.bf16.f32 "
                 "{%0,%1,%2,%3}, {%4,%5,%6,%7}, {%8,%9}, {%0,%1,%2,%3};"
                 : "+f"(c[0]), "+f"(c[1]), "+f"(c[2]), "+f"(c[3])
                 : "r"(a[0]), "r"(a[1]), "r"(a[2]), "r"(a[3]),
                   "r"(b[0]), "r"(b[1]));
}

// ---------------- fused LayerNorm ----------------
__global__ __launch_bounds__(256)
void ln_kernel(const float* __restrict__ x, const float* __restrict__ g,
               const float* __restrict__ b, float* __restrict__ y)
{
    __shared__ float red[8];
    int row = blockIdx.x;
    int t = threadIdx.x;
    const float4* xr = (const float4*)(x + (size_t)row * EDIM);
    float4 v = xr[t];
    float s = v.x + v.y + v.z + v.w;
    #pragma unroll
    for (int o = 16; o > 0; o >>= 1) s += __shfl_xor_sync(0xffffffffu, s, o);
    if ((t & 31) == 0) red[t >> 5] = s;
    __syncthreads();
    float tot = 0.f;
    #pragma unroll
    for (int i = 0; i < 8; i++) tot += red[i];
    float mean = tot * (1.0f / EDIM);
    float dx = v.x - mean, dy = v.y - mean, dz = v.z - mean, dw = v.w - mean;
    float s2 = dx*dx + dy*dy + dz*dz + dw*dw;
    __syncthreads();
    #pragma unroll
    for (int o = 16; o > 0; o >>= 1) s2 += __shfl_xor_sync(0xffffffffu, s2, o);
    if ((t & 31) == 0) red[t >> 5] = s2;
    __syncthreads();
    float tot2 = 0.f;
    #pragma unroll
    for (int i = 0; i < 8; i++) tot2 += red[i];
    float r = rsqrtf(tot2 * (1.0f / EDIM) + 1e-5f);
    float4 g4 = ((const float4*)g)[t];
    float4 b4 = ((const float4*)b)[t];
    float4 o4;
    o4.x = dx * r * g4.x + b4.x;
    o4.y = dy * r * g4.y + b4.y;
    o4.z = dz * r * g4.z + b4.z;
    o4.w = dw * r * g4.w + b4.w;
    ((float4*)(y + (size_t)row * EDIM))[t] = o4;
}

// ---------------- fp32 -> bf16 hi/lo split ----------------
__global__ __launch_bounds__(256)
void split_kernel(const float* __restrict__ x, __nv_bfloat16* __restrict__ hi,
                  __nv_bfloat16* __restrict__ lo, int n4)
{
    int i = blockIdx.x * 256 + threadIdx.x;
    if (i >= n4) return;
    float4 v = ((const float4*)x)[i];
    __nv_bfloat16 h0 = __float2bfloat16(v.x);
    __nv_bfloat16 h1 = __float2bfloat16(v.y);
    __nv_bfloat16 h2 = __float2bfloat16(v.z);
    __nv_bfloat16 h3 = __float2bfloat16(v.w);
    __nv_bfloat16 l0 = __float2bfloat16(v.x - __bfloat162float(h0));
    __nv_bfloat16 l1 = __float2bfloat16(v.y - __bfloat162float(h1));
    __nv_bfloat16 l2 = __float2bfloat16(v.z - __bfloat162float(h2));
    __nv_bfloat16 l3 = __float2bfloat16(v.w - __bfloat162float(h3));
    __nv_bfloat162* H = (__nv_bfloat162*)hi;
    __nv_bfloat162* L = (__nv_bfloat162*)lo;
    H[i*2]   = __nv_bfloat162(h0, h1);
    H[i*2+1] = __nv_bfloat162(h2, h3);
    L[i*2]   = __nv_bfloat162(l0, l1);
    L[i*2+1] = __nv_bfloat162(l2, l3);
}

// ---------------- weight transpose + split: W[K,N] -> T[N,K] hi/lo ----------
__global__ __launch_bounds__(256)
void tsplit_kernel(const float* __restrict__ W, __nv_bfloat16* __restrict__ Th,
                   __nv_bfloat16* __restrict__ Tl, int K, int N)
{
    __shared__ float tile[32][33];
    int bx = blockIdx.x * 32;   // N
    int by = blockIdx.y * 32;   // K
    int tx = threadIdx.x, ty = threadIdx.y;
    #pragma unroll
    for (int j = 0; j < 32; j += 8)
        tile[ty + j][tx] = W[(size_t)(by + ty + j) * N + bx + tx];
    __syncthreads();
    #pragma unroll
    for (int j = 0; j < 32; j += 8) {
        float v = tile[tx][ty + j];
        __nv_bfloat16 h = __float2bfloat16(v);
        __nv_bfloat16 l = __float2bfloat16(v - __bfloat162float(h));
        size_t o = (size_t)(bx + ty + j) * K + by + tx;
        Th[o] = h;
        Tl[o] = l;
    }
}

// ---------------- mma.sync bf16x3 GEMM ---------------------------------------
// C[M,N] = A[M,K] @ B[N,K]^T with A,B as bf16 hi/lo splits.
// Tile 128x128, K-chunk 64 (one SW128 row), cp.async double buffer,
// 8 warps in 2(m) x 4(n); warp tile 64x32. Per k16: hh + hl + lh MMAs.
#define G_TILE_B     16384     // one 128x64 bf16 tile (SW128 rows of 128B)
#define G_STAGE_B    (4*G_TILE_B)
#define G_SMEM_TOTAL (2*G_STAGE_B)

__global__ __launch_bounds__(256, 1)
void gemm_mma(const __nv_bfloat16* __restrict__ Ah, const __nv_bfloat16* __restrict__ Al,
              const __nv_bfloat16* __restrict__ Bh, const __nv_bfloat16* __restrict__ Bl,
              float* __restrict__ C, const float* __restrict__ bias,
              const float* __restrict__ resid, int relu, int N, int K)
{
    extern __shared__ __align__(1024) char smem[];
    const uint32_t sb = smem_u32(smem);
    const int tid  = threadIdx.x;
    const int wid  = tid >> 5, lane = tid & 31;
    const int wm   = wid >> 2;          // 0..1  (64 rows each)
    const int wn   = wid & 3;           // 0..3  (32 cols each)
    const int bm = blockIdx.y, bn = blockIdx.x;

    const size_t arow0 = (size_t)bm * 128;
    const size_t brow0 = (size_t)bn * 128;

    auto load_stage = [&](int s, int k0) {
        uint32_t base = sb + s * G_STAGE_B;
        #pragma unroll
        for (int it = 0; it < 16; it++) {
            int c   = tid + it * 256;
            int tl  = c >> 10;          // which of the 4 tiles
            int idx = c & 1023;
            int r   = idx >> 3;         // row 0..127
            int c16 = idx & 7;          // 16B col 0..7
            uint32_t dst = base + tl * G_TILE_B + SWZ128(r * 128 + c16 * 16);
            const __nv_bfloat16* src;
            if      (tl == 0) src = Ah + (arow0 + r) * K + k0 + c16 * 8;
            else if (tl == 1) src = Al + (arow0 + r) * K + k0 + c16 * 8;
            else if (tl == 2) src = Bh + (brow0 + r) * K + k0 + c16 * 8;
            else              src = Bl + (brow0 + r) * K + k0 + c16 * 8;
            CP_ASYNC16(dst, src);
        }
        CP_COMMIT();
    };

    float acc[4][4][4];
    #pragma unroll
    for (int mf = 0; mf < 4; mf++)
        #pragma unroll
        for (int nf = 0; nf < 4; nf++)
            #pragma unroll
            for (int e = 0; e < 4; e++) acc[mf][nf][e] = 0.f;

    const int nch = K >> 6;
    load_stage(0, 0);

    // precomputed intra-tile fragment offsets (lane-dependent)
    const int a_r  = (lane & 7) + ((lane >> 3) & 1) * 8;  // + mf*16 + wm*64
    const int a_cb = (lane >> 4) * 16;                    // + ks*32
    const int b_l  = lane & 15;
    const int b_r  = b_l & 7;                             // + nf*8 + wn*32
    const int b_cb = ((b_l >> 3) & 1) * 16;               // + ks*32

    for (int i = 0; i < nch; i++) {
        if (i + 1 < nch) { load_stage((i + 1) & 1, (i + 1) << 6); CP_WAIT(1); }
        else             { CP_WAIT(0); }
        __syncthreads();

        uint32_t tAh = sb + (i & 1) * G_STAGE_B;
        uint32_t tAl = tAh + G_TILE_B;
        uint32_t tBh = tAh + 2 * G_TILE_B;
        uint32_t tBl = tAh + 3 * G_TILE_B;

        #pragma unroll
        for (int ks = 0; ks < 4; ks++) {
            uint32_t rah[4][4], ral[4][4], rbh[4][2], rbl[4][2];
            #pragma unroll
            for (int mf = 0; mf < 4; mf++) {
                uint32_t off = SWZ128((wm * 64 + mf * 16 + a_r) * 128 + ks * 32 + a_cb);
                ldsm_x4(rah[mf], tAh + off);
                ldsm_x4(ral[mf], tAl + off);
            }
            #pragma unroll
            for (int nf = 0; nf < 4; nf++) {
                uint32_t off = SWZ128((wn * 32 + nf * 8 + b_r) * 128 + ks * 32 + b_cb);
                ldsm_x2(rbh[nf], tBh + off);
                ldsm_x2(rbl[nf], tBl + off);
            }
            #pragma unroll
            for (int mf = 0; mf < 4; mf++)
                #pragma unroll
                for (int nf = 0; nf < 4; nf++) {
                    mma16816(acc[mf][nf], rah[mf], rbh[nf]);
                    mma16816(acc[mf][nf], rah[mf], rbl[nf]);
                    mma16816(acc[mf][nf], ral[mf], rbh[nf]);
                }
        }
        __syncthreads();
    }

    // epilogue: thread t holds (r0, c), (r0, c+1), (r0+8, c), (r0+8, c+1)
    int rbase = bm * 128 + wm * 64 + (lane >> 2);
    int cbase = bn * 128 + wn * 32 + (lane & 3) * 2;
    #pragma unroll
    for (int mf = 0; mf < 4; mf++) {
        #pragma unroll
        for (int half = 0; half < 2; half++) {
            int row = rbase + mf * 16 + half * 8;
            float* crow = C + (size_t)row * N;
            const float* rrow = resid ? resid + (size_t)row * N : nullptr;
            #pragma unroll
            for (int nf = 0; nf < 4; nf++) {
                int col = cbase + nf * 8;
                float2 o;
                o.x = acc[mf][nf][half * 2 + 0];
                o.y = acc[mf][nf][half * 2 + 1];
                if (bias) {
                    float2 bb = *(const float2*)(bias + col);
                    o.x += bb.x; o.y += bb.y;
                }
                if (relu) { o.x = fmaxf(o.x, 0.f); o.y = fmaxf(o.y, 0.f); }
                if (rrow) {
                    float2 rr = *(const float2*)(rrow + col);
                    o.x += rr.x; o.y += rr.y;
                }
                *(float2*)(crow + col) = o;
            }
        }
    }
}

// ---------------- causal flash attention, fp32 -------------------------------
__global__ __launch_bounds__(256)
void attn_kernel(const float* __restrict__ Q, const float* __restrict__ K,
                 const float* __restrict__ V, float* __restrict__ O)
{
    __shared__ float Ks[64][64];
    __shared__ float Vs[64][64];
    int tid = threadIdx.x;
    int qr = tid >> 2;
    int c  = tid & 3;
    int qt = blockIdx.x;
    int h  = blockIdx.y;
    int b  = blockIdx.z;
    int tq = qt * 64 + qr;
    size_t qoff = ((size_t)(b * TSEQ + tq)) * EDIM + h * HDIM;

    float qreg[64];
    #pragma unroll
    for (int d = 0; d < 64; d += 4) {
        float4 t4 = *(const float4*)(Q + qoff + d);
        qreg[d] = t4.x; qreg[d+1] = t4.y; qreg[d+2] = t4.z; qreg[d+3] = t4.w;
    }

    float m = -1e30f, l = 0.f;
    float o[16];
    #pragma unroll
    for (int i = 0; i < 16; i++) o[i] = 0.f;

    int ntiles = qt + 1;
    for (int kt = 0; kt < ntiles; kt++) {
        int kbase = kt * 64;
        __syncthreads();
        #pragma unroll
        for (int it = 0; it < 4; it++) {
            int idx = tid + it * 256;
            int j  = idx >> 4;
            int d4 = (idx & 15) << 2;
            size_t goff = ((size_t)(b * TSEQ + kbase + j)) * EDIM + h * HDIM + d4;
            *(float4*)&Ks[j][d4] = *(const float4*)(K + goff);
            *(float4*)&Vs[j][d4] = *(const float4*)(V + goff);
        }
        __syncthreads();

        float sreg[16];
        #pragma unroll
        for (int jj = 0; jj < 16; jj++) {
            int j = c * 16 + jj;
            float s = 0.f;
            #pragma unroll
            for (int d = 0; d < 64; d += 4) {
                float4 k4 = *(const float4*)&Ks[j][d];
                s += qreg[d]   * k4.x + qreg[d+1] * k4.y
                   + qreg[d+2] * k4.z + qreg[d+3] * k4.w;
            }
            s *= 0.125f;
            if (kbase + j > tq) s = -1e30f;
            sreg[jj] = s;
        }

        float tm = sreg[0];
        #pragma unroll
        for (int jj = 1; jj < 16; jj++) tm = fmaxf(tm, sreg[jj]);
        tm = fmaxf(tm, __shfl_xor_sync(0xffffffffu, tm, 1));
        tm = fmaxf(tm, __shfl_xor_sync(0xffffffffu, tm, 2));
        float mn = fmaxf(m, tm);
        float corr = __expf(m - mn);
        float ls = 0.f;
        #pragma unroll
        for (int jj = 0; jj < 16; jj++) { sreg[jj] = __expf(sreg[jj] - mn); ls += sreg[jj]; }
        ls += __shfl_xor_sync(0xffffffffu, ls, 1);
        ls += __shfl_xor_sync(0xffffffffu, ls, 2);
        l = l * corr + ls;
        m = mn;
        #pragma unroll
        for (int i = 0; i < 16; i++) o[i] *= corr;

        #pragma unroll
        for (int cs = 0; cs < 4; cs++) {
            #pragma unroll
            for (int jj = 0; jj < 16; jj++) {
                float pv = __shfl_sync(0xffffffffu, sreg[jj], cs, 4);
                const float* vrow = &Vs[cs * 16 + jj][c * 16];
                #pragma unroll
                for (int i4 = 0; i4 < 16; i4 += 4) {
                    float4 v4 = *(const float4*)(vrow + i4);
                    o[i4]   += pv * v4.x;
                    o[i4+1] += pv * v4.y;
                    o[i4+2] += pv * v4.z;
                    o[i4+3] += pv * v4.w;
                }
            }
        }
    }

    float inv = 1.f / l;
    size_t ooff = qoff + c * 16;
    #pragma unroll
    for (int i4 = 0; i4 < 16; i4 += 4) {
        float4 t4;
        t4.x = o[i4] * inv;   t4.y = o[i4+1] * inv;
        t4.z = o[i4+2] * inv; t4.w = o[i4+3] * inv;
        *(float4*)(O + ooff + i4) = t4;
    }
}

// ---------------- launch -----------------------------------------------------
extern "C" void kernel_launch(void* const* d_in, const int* in_sizes, int n_in,
                              void* d_out, int out_size)
{
    const float* x    = (const float*)d_in[0];
    const float* ln1g = (const float*)d_in[1];
    const float* ln1b = (const float*)d_in[2];
    const float* Wq   = (const float*)d_in[3];
    const float* Wk   = (const float*)d_in[4];
    const float* Wv   = (const float*)d_in[5];
    const float* Wo   = (const float*)d_in[6];
    const float* bo   = (const float*)d_in[7];
    const float* ln2g = (const float*)d_in[8];
    const float* ln2b = (const float*)d_in[9];
    const float* W1   = (const float*)d_in[10];
    const float* b1   = (const float*)d_in[11];
    const float* W2   = (const float*)d_in[12];
    const float* b2   = (const float*)d_in[13];
    float* out = (float*)d_out;

    float *xn, *q, *k, *v, *att, *x1, *h, *hid;
    __nv_bfloat16 *ah, *al, *wqh, *wql, *wkh, *wkl, *wvh, *wvl, *woh, *wol,
                  *w1h, *w1l, *w2h, *w2l;
    cudaGetSymbolAddress((void**)&xn,  g_xn);
    cudaGetSymbolAddress((void**)&q,   g_q);
    cudaGetSymbolAddress((void**)&k,   g_k);
    cudaGetSymbolAddress((void**)&v,   g_v);
    cudaGetSymbolAddress((void**)&att, g_att);
    cudaGetSymbolAddress((void**)&x1,  g_x1);
    cudaGetSymbolAddress((void**)&h,   g_h);
    cudaGetSymbolAddress((void**)&hid, g_hid);
    cudaGetSymbolAddress((void**)&ah,  g_ah);
    cudaGetSymbolAddress((void**)&al,  g_al);
    cudaGetSymbolAddress((void**)&wqh, g_wqh);
    cudaGetSymbolAddress((void**)&wql, g_wql);
    cudaGetSymbolAddress((void**)&wkh, g_wkh);
    cudaGetSymbolAddress((void**)&wkl, g_wkl);
    cudaGetSymbolAddress((void**)&wvh, g_wvh);
    cudaGetSymbolAddress((void**)&wvl, g_wvl);
    cudaGetSymbolAddress((void**)&woh, g_woh);
    cudaGetSymbolAddress((void**)&wol, g_wol);
    cudaGetSymbolAddress((void**)&w1h, g_w1h);
    cudaGetSymbolAddress((void**)&w1l, g_w1l);
    cudaGetSymbolAddress((void**)&w2h, g_w2h);
    cudaGetSymbolAddress((void**)&w2l, g_w2l);

    cudaFuncSetAttribute(gemm_mma, cudaFuncAttributeMaxDynamicSharedMemorySize,
                         G_SMEM_TOTAL);

    dim3 tb(32, 8);
    // weight preprocessing: transpose + bf16 hi/lo split
    tsplit_kernel<<<dim3(EDIM/32, EDIM/32), tb>>>(Wq, wqh, wql, EDIM, EDIM);
    tsplit_kernel<<<dim3(EDIM/32, EDIM/32), tb>>>(Wk, wkh, wkl, EDIM, EDIM);
    tsplit_kernel<<<dim3(EDIM/32, EDIM/32), tb>>>(Wv, wvh, wvl, EDIM, EDIM);
    tsplit_kernel<<<dim3(EDIM/32, EDIM/32), tb>>>(Wo, woh, wol, EDIM, EDIM);
    tsplit_kernel<<<dim3(FDIM/32, EDIM/32), tb>>>(W1, w1h, w1l, EDIM, FDIM);
    tsplit_kernel<<<dim3(EDIM/32, FDIM/32), tb>>>(W2, w2h, w2l, FDIM, EDIM);

    // 1. xn = LN1(x); split
    ln_kernel<<<MTOK, 256>>>(x, ln1g, ln1b, xn);
    split_kernel<<<(MTOK*EDIM/4 + 255)/256, 256>>>(xn, ah, al, MTOK*EDIM/4);

    // 2. Q,K,V
    dim3 gE(EDIM/128, MTOK/128);
    gemm_mma<<<gE, 256, G_SMEM_TOTAL>>>(ah, al, wqh, wql, q, nullptr, nullptr, 0, EDIM, EDIM);
    gemm_mma<<<gE, 256, G_SMEM_TOTAL>>>(ah, al, wkh, wkl, k, nullptr, nullptr, 0, EDIM, EDIM);
    gemm_mma<<<gE, 256, G_SMEM_TOTAL>>>(ah, al, wvh, wvl, v, nullptr, nullptr, 0, EDIM, EDIM);

    // 3. causal MHA
    attn_kernel<<<dim3(TSEQ/64, NHEAD, BATCH), 256>>>(q, k, v, att);

    // 4. x1 = att @ Wo + bo + x
    split_kernel<<<(MTOK*EDIM/4 + 255)/256, 256>>>(att, ah, al, MTOK*EDIM/4);
    gemm_mma<<<gE, 256, G_SMEM_TOTAL>>>(ah, al, woh, wol, x1, bo, x, 0, EDIM, EDIM);

    // 5. h = LN2(x1)
    ln_kernel<<<MTOK, 256>>>(x1, ln2g, ln2b, h);
    split_kernel<<<(MTOK*EDIM/4 + 255)/256, 256>>>(h, ah, al, MTOK*EDIM/4);

    // 6. hid = relu(h @ W1 + b1)
    dim3 gF(FDIM/128, MTOK/128);
    gemm_mma<<<gF, 256, G_SMEM_TOTAL>>>(ah, al, w1h, w1l, hid, b1, nullptr, 1, FDIM, EDIM);

    // 7. out = hid @ W2 + b2 + x1
    split_kernel<<<(MTOK*FDIM/4 + 255)/256, 256>>>(hid, ah, al, MTOK*FDIM/4);
    gemm_mma<<<gE, 256, G_SMEM_TOTAL>>>(ah, al, w2h, w2l, out, b2, x1, 0, EDIM, FDIM);
}

// round 4
// speedup vs baseline: 6.1229x; 4.0251x over previous
#include <cuda_runtime.h>
#include <cuda_bf16.h>
#include <cstdint>
#include <cstddef>

// Problem dims
#define BATCH 2
#define TSEQ  2048
#define EDIM  1024
#define FDIM  4096
#define NHEAD 16
#define HDIM  64
#define MTOK  (BATCH*TSEQ)   // 4096 rows

// ---------------- scratch (device globals: allocation-free) ----------------
__device__ float g_x1 [MTOK*EDIM];
__device__ __nv_bfloat16 g_ah [MTOK*FDIM];
__device__ __nv_bfloat16 g_al [MTOK*FDIM];
__device__ __nv_bfloat16 g_bh [MTOK*FDIM];
__device__ __nv_bfloat16 g_bl [MTOK*FDIM];
__device__ __nv_bfloat16 g_qh [MTOK*EDIM], g_ql [MTOK*EDIM];
__device__ __nv_bfloat16 g_kh [MTOK*EDIM], g_kl [MTOK*EDIM];
__device__ __nv_bfloat16 g_vh [MTOK*EDIM], g_vl [MTOK*EDIM];
__device__ __nv_bfloat16 g_wqh[EDIM*EDIM], g_wql[EDIM*EDIM];
__device__ __nv_bfloat16 g_wkh[EDIM*EDIM], g_wkl[EDIM*EDIM];
__device__ __nv_bfloat16 g_wvh[EDIM*EDIM], g_wvl[EDIM*EDIM];
__device__ __nv_bfloat16 g_woh[EDIM*EDIM], g_wol[EDIM*EDIM];
__device__ __nv_bfloat16 g_w1h[FDIM*EDIM], g_w1l[FDIM*EDIM];
__device__ __nv_bfloat16 g_w2h[EDIM*FDIM], g_w2l[EDIM*FDIM];

// ---------------- PTX helpers (sm_80-compatible only) ----------------
__device__ __forceinline__ uint32_t smem_u32(const void* p) {
    uint32_t a;
    asm("{ .reg .u64 t; cvta.to.shared.u64 t, %1; cvt.u32.u64 %0, t; }" : "=r"(a) : "l"(p));
    return a;
}
#define SWZ128(o) ((o) ^ ((((uint32_t)(o)) >> 3) & 0x70u))

#define CP_ASYNC16(dst, src) \
    asm volatile("cp.async.cg.shared.global [%0], [%1], 16;" :: "r"(dst), "l"(src) : "memory")
#define CP_COMMIT()  asm volatile("cp.async.commit_group;" ::: "memory")
#define CP_WAIT(n)   asm volatile("cp.async.wait_group %0;" :: "n"(n) : "memory")

__device__ __forceinline__ void ldsm_x4(uint32_t* r, uint32_t addr) {
    asm volatile("ldmatrix.sync.aligned.m8n8.x4.shared.b16 {%0,%1,%2,%3}, [%4];"
                 : "=r"(r[0]), "=r"(r[1]), "=r"(r[2]), "=r"(r[3]) : "r"(addr));
}
__device__ __forceinline__ void ldsm_x2(uint32_t* r, uint32_t addr) {
    asm volatile("ldmatrix.sync.aligned.m8n8.x2.shared.b16 {%0,%1}, [%2];"
                 : "=r"(r[0]), "=r"(r[1]) : "r"(addr));
}
__device__ __forceinline__ void ldsm_x2t(uint32_t* r, uint32_t addr) {
    asm volatile("ldmatrix.sync.aligned.m8n8.x2.trans.shared.b16 {%0,%1}, [%2];"
                 : "=r"(r[0]), "=r"(r[1]) : "r"(addr));
}
__device__ __forceinline__ void mma16816(float* c, const uint32_t* a, const uint32_t* b) {
    asm volatile("mma.sync.aligned.m16n8k16.row.col.f32.bf16.bf16.f32 "
                 "{%0,%1,%2,%3}, {%4,%5,%6,%7}, {%8,%9}, {%0,%1,%2,%3};"
                 : "+f"(c[0]), "+f"(c[1]), "+f"(c[2]), "+f"(c[3])
                 : "r"(a[0]), "r"(a[1]), "r"(a[2]), "r"(a[3]),
                   "r"(b[0]), "r"(b[1]));
}
__device__ __forceinline__ uint32_t packbf2(float a, float b) {
    __nv_bfloat162 t(__float2bfloat16(a), __float2bfloat16(b));
    return *(uint32_t*)&t;
}

// ---------------- fused LayerNorm -> bf16 hi/lo split ----------------
__global__ __launch_bounds__(256)
void ln_split_kernel(const float* __restrict__ x, const float* __restrict__ g,
                     const float* __restrict__ b, __nv_bfloat16* __restrict__ yh,
                     __nv_bfloat16* __restrict__ yl)
{
    __shared__ float red[8];
    int row = blockIdx.x;
    int t = threadIdx.x;
    const float4* xr = (const float4*)(x + (size_t)row * EDIM);
    float4 v = xr[t];
    float s = v.x + v.y + v.z + v.w;
    #pragma unroll
    for (int o = 16; o > 0; o >>= 1) s += __shfl_xor_sync(0xffffffffu, s, o);
    if ((t & 31) == 0) red[t >> 5] = s;
    __syncthreads();
    float tot = 0.f;
    #pragma unroll
    for (int i = 0; i < 8; i++) tot += red[i];
    float mean = tot * (1.0f / EDIM);
    float dx = v.x - mean, dy = v.y - mean, dz = v.z - mean, dw = v.w - mean;
    float s2 = dx*dx + dy*dy + dz*dz + dw*dw;
    __syncthreads();
    #pragma unroll
    for (int o = 16; o > 0; o >>= 1) s2 += __shfl_xor_sync(0xffffffffu, s2, o);
    if ((t & 31) == 0) red[t >> 5] = s2;
    __syncthreads();
    float tot2 = 0.f;
    #pragma unroll
    for (int i = 0; i < 8; i++) tot2 += red[i];
    float r = rsqrtf(tot2 * (1.0f / EDIM) + 1e-5f);
    float4 g4 = ((const float4*)g)[t];
    float4 b4 = ((const float4*)b)[t];
    float o0 = dx * r * g4.x + b4.x;
    float o1 = dy * r * g4.y + b4.y;
    float o2 = dz * r * g4.z + b4.z;
    float o3 = dw * r * g4.w + b4.w;
    __nv_bfloat16 h0 = __float2bfloat16(o0), h1 = __float2bfloat16(o1);
    __nv_bfloat16 h2 = __float2bfloat16(o2), h3 = __float2bfloat16(o3);
    size_t base = (size_t)row * EDIM + t * 4;
    *(__nv_bfloat162*)(yh + base)     = __nv_bfloat162(h0, h1);
    *(__nv_bfloat162*)(yh + base + 2) = __nv_bfloat162(h2, h3);
    *(__nv_bfloat162*)(yl + base) =
        __nv_bfloat162(__float2bfloat16(o0 - __bfloat162float(h0)),
                       __float2bfloat16(o1 - __bfloat162float(h1)));
    *(__nv_bfloat162*)(yl + base + 2) =
        __nv_bfloat162(__float2bfloat16(o2 - __bfloat162float(h2)),
                       __float2bfloat16(o3 - __bfloat162float(h3)));
}

// ---------------- weight transpose + split: W[K,N] -> T[N,K] hi/lo ----------
__global__ __launch_bounds__(256)
void tsplit_kernel(const float* __restrict__ W, __nv_bfloat16* __restrict__ Th,
                   __nv_bfloat16* __restrict__ Tl, int K, int N)
{
    __shared__ float tile[32][33];
    int bx = blockIdx.x * 32;   // N
    int by = blockIdx.y * 32;   // K
    int tx = threadIdx.x, ty = threadIdx.y;
    #pragma unroll
    for (int j = 0; j < 32; j += 8)
        tile[ty + j][tx] = W[(size_t)(by + ty + j) * N + bx + tx];
    __syncthreads();
    #pragma unroll
    for (int j = 0; j < 32; j += 8) {
        float v = tile[tx][ty + j];
        __nv_bfloat16 h = __float2bfloat16(v);
        __nv_bfloat16 l = __float2bfloat16(v - __bfloat162float(h));
        size_t o = (size_t)(bx + ty + j) * K + by + tx;
        Th[o] = h;
        Tl[o] = l;
    }
}

// ---------------- mma.sync bf16x3 GEMM ---------------------------------------
#define G_TILE_B     16384
#define G_STAGE_B    (4*G_TILE_B)
#define G_SMEM_TOTAL (2*G_STAGE_B)

__global__ __launch_bounds__(256, 1)
void gemm_mma(const __nv_bfloat16* __restrict__ Ah, const __nv_bfloat16* __restrict__ Al,
              const __nv_bfloat16* __restrict__ Bh, const __nv_bfloat16* __restrict__ Bl,
              float* __restrict__ C, __nv_bfloat16* __restrict__ Oh,
              __nv_bfloat16* __restrict__ Ol, const float* __restrict__ bias,
              const float* __restrict__ resid, int relu, int N, int K)
{
    extern __shared__ __align__(1024) char smem[];
    const uint32_t sb = smem_u32(smem);
    const int tid  = threadIdx.x;
    const int wid  = tid >> 5, lane = tid & 31;
    const int wm   = wid >> 2;
    const int wn   = wid & 3;
    const int bm = blockIdx.y, bn = blockIdx.x;

    const size_t arow0 = (size_t)bm * 128;
    const size_t brow0 = (size_t)bn * 128;

    auto load_stage = [&](int s, int k0) {
        uint32_t base = sb + s * G_STAGE_B;
        #pragma unroll
        for (int it = 0; it < 16; it++) {
            int c   = tid + it * 256;
            int tl  = c >> 10;
            int idx = c & 1023;
            int r   = idx >> 3;
            int c16 = idx & 7;
            uint32_t dst = base + tl * G_TILE_B + SWZ128(r * 128 + c16 * 16);
            const __nv_bfloat16* src;
            if      (tl == 0) src = Ah + (arow0 + r) * K + k0 + c16 * 8;
            else if (tl == 1) src = Al + (arow0 + r) * K + k0 + c16 * 8;
            else if (tl == 2) src = Bh + (brow0 + r) * K + k0 + c16 * 8;
            else              src = Bl + (brow0 + r) * K + k0 + c16 * 8;
            CP_ASYNC16(dst, src);
        }
        CP_COMMIT();
    };

    float acc[4][4][4];
    #pragma unroll
    for (int mf = 0; mf < 4; mf++)
        #pragma unroll
        for (int nf = 0; nf < 4; nf++)
            #pragma unroll
            for (int e = 0; e < 4; e++) acc[mf][nf][e] = 0.f;

    const int nch = K >> 6;
    load_stage(0, 0);

    const int a_r  = (lane & 7) + ((lane >> 3) & 1) * 8;
    const int a_cb = (lane >> 4) * 16;
    const int b_l  = lane & 15;
    const int b_r  = b_l & 7;
    const int b_cb = ((b_l >> 3) & 1) * 16;

    for (int i = 0; i < nch; i++) {
        if (i + 1 < nch) { load_stage((i + 1) & 1, (i + 1) << 6); CP_WAIT(1); }
        else             { CP_WAIT(0); }
        __syncthreads();

        uint32_t tAh = sb + (i & 1) * G_STAGE_B;
        uint32_t tAl = tAh + G_TILE_B;
        uint32_t tBh = tAh + 2 * G_TILE_B;
        uint32_t tBl = tAh + 3 * G_TILE_B;

        #pragma unroll
        for (int ks = 0; ks < 4; ks++) {
            uint32_t rah[4][4], ral[4][4], rbh[4][2], rbl[4][2];
            #pragma unroll
            for (int mf = 0; mf < 4; mf++) {
                uint32_t off = SWZ128((wm * 64 + mf * 16 + a_r) * 128 + ks * 32 + a_cb);
                ldsm_x4(rah[mf], tAh + off);
                ldsm_x4(ral[mf], tAl + off);
            }
            #pragma unroll
            for (int nf = 0; nf < 4; nf++) {
                uint32_t off = SWZ128((wn * 32 + nf * 8 + b_r) * 128 + ks * 32 + b_cb);
                ldsm_x2(rbh[nf], tBh + off);
                ldsm_x2(rbl[nf], tBl + off);
            }
            #pragma unroll
            for (int mf = 0; mf < 4; mf++)
                #pragma unroll
                for (int nf = 0; nf < 4; nf++) {
                    mma16816(acc[mf][nf], rah[mf], rbh[nf]);
                    mma16816(acc[mf][nf], rah[mf], rbl[nf]);
                    mma16816(acc[mf][nf], ral[mf], rbh[nf]);
                }
        }
        __syncthreads();
    }

    int rbase = bm * 128 + wm * 64 + (lane >> 2);
    int cbase = bn * 128 + wn * 32 + (lane & 3) * 2;
    #pragma unroll
    for (int mf = 0; mf < 4; mf++) {
        #pragma unroll
        for (int half = 0; half < 2; half++) {
            int row = rbase + mf * 16 + half * 8;
            #pragma unroll
            for (int nf = 0; nf < 4; nf++) {
                int col = cbase + nf * 8;
                float ox = acc[mf][nf][half * 2 + 0];
                float oy = acc[mf][nf][half * 2 + 1];
                if (bias) {
                    float2 bb = *(const float2*)(bias + col);
                    ox += bb.x; oy += bb.y;
                }
                if (relu) { ox = fmaxf(ox, 0.f); oy = fmaxf(oy, 0.f); }
                if (resid) {
                    float2 rr = *(const float2*)(resid + (size_t)row * N + col);
                    ox += rr.x; oy += rr.y;
                }
                if (C) {
                    float2 o2; o2.x = ox; o2.y = oy;
                    *(float2*)(C + (size_t)row * N + col) = o2;
                }
                if (Oh) {
                    __nv_bfloat16 hx = __float2bfloat16(ox);
                    __nv_bfloat16 hy = __float2bfloat16(oy);
                    *(__nv_bfloat162*)(Oh + (size_t)row * N + col) = __nv_bfloat162(hx, hy);
                    *(__nv_bfloat162*)(Ol + (size_t)row * N + col) =
                        __nv_bfloat162(__float2bfloat16(ox - __bfloat162float(hx)),
                                       __float2bfloat16(oy - __bfloat162float(hy)));
                }
            }
        }
    }
}

// ---------------- tensor-core causal flash attention --------------------------
// Block: 128 queries of one (b,h); 8 warps, warp w owns q rows [w*16, w*16+16).
// K tiles of 64 keys, double-buffered cp.async. bf16x3 for QK^T and PV.
// smem: Qh[0,16K) Ql[16K,32K); stage s at 32K+s*32K: Kh+0 Kl+8K Vh+16K Vl+24K.
#define AT_SMEM (32768 + 2*32768)

__global__ __launch_bounds__(256, 1)
void attn_mma(const __nv_bfloat16* __restrict__ Qh, const __nv_bfloat16* __restrict__ Ql,
              const __nv_bfloat16* __restrict__ Kh, const __nv_bfloat16* __restrict__ Kl,
              const __nv_bfloat16* __restrict__ Vh, const __nv_bfloat16* __restrict__ Vl,
              __nv_bfloat16* __restrict__ Oh, __nv_bfloat16* __restrict__ Ol)
{
    extern __shared__ __align__(1024) char smem[];
    const uint32_t sb = smem_u32(smem);
    const int tid = threadIdx.x, wid = tid >> 5, lane = tid & 31;
    const int qt = blockIdx.x, h = blockIdx.y, b = blockIdx.z;
    const int q0 = qt * 128;
    const size_t hoff = (size_t)h * HDIM;

    // Q tiles (hi, lo): 2 x 128 rows x 8 chunks
    #pragma unroll
    for (int it = 0; it < 8; it++) {
        int idx = tid + it * 256;
        int tl = idx >> 10, r = (idx >> 3) & 127, c16 = idx & 7;
        uint32_t dst = sb + tl * 16384 + SWZ128(r * 128 + c16 * 16);
        const __nv_bfloat16* src =
            (tl ? Ql : Qh) + (size_t)(b * TSEQ + q0 + r) * EDIM + hoff + c16 * 8;
        CP_ASYNC16(dst, src);
    }
    auto load_kv = [&](int s, int kbase) {
        uint32_t base = sb + 32768 + s * 32768;
        #pragma unroll
        for (int it = 0; it < 8; it++) {
            int idx = tid + it * 256;
            int tl = idx >> 9, r = (idx >> 3) & 63, c16 = idx & 7;
            uint32_t dst = base + tl * 8192 + SWZ128(r * 128 + c16 * 16);
            size_t go = (size_t)(b * TSEQ + kbase + r) * EDIM + hoff + c16 * 8;
            const __nv_bfloat16* p;
            if (tl == 0) p = Kh + go; else if (tl == 1) p = Kl + go;
            else if (tl == 2) p = Vh + go; else p = Vl + go;
            CP_ASYNC16(dst, p);
        }
        CP_COMMIT();
    };
    load_kv(0, 0);   // same group as Q

    const int a_r  = (lane & 7) + ((lane >> 3) & 1) * 8;
    const int a_cb = (lane >> 4) * 16;
    const int b_l  = lane & 15;
    const int b_r  = b_l & 7;
    const int b_cb = ((b_l >> 3) & 1) * 16;
    const int rA   = q0 + wid * 16 + (lane >> 2);
    const int wrowmax = q0 + wid * 16 + 15;

    float mrow[2] = {-1e30f, -1e30f};
    float lrow[2] = {0.f, 0.f};
    float o[8][4];
    #pragma unroll
    for (int nf = 0; nf < 8; nf++)
        #pragma unroll
        for (int e = 0; e < 4; e++) o[nf][e] = 0.f;
    uint32_t rah[4][4], ral[4][4];

    const int nkt = (q0 + 128) / 64;
    for (int kt = 0; kt < nkt; kt++) {
        if (kt + 1 < nkt) { load_kv((kt + 1) & 1, (kt + 1) * 64); CP_WAIT(1); }
        else              { CP_WAIT(0); }
        __syncthreads();
        if (kt == 0) {
            #pragma unroll
            for (int ks = 0; ks < 4; ks++) {
                uint32_t off = SWZ128((wid * 16 + a_r) * 128 + ks * 32 + a_cb);
                ldsm_x4(rah[ks], sb + off);
                ldsm_x4(ral[ks], sb + 16384 + off);
            }
        }
        if (kt * 64 <= wrowmax) {
            uint32_t kb = sb + 32768 + (kt & 1) * 32768;
            float s[8][4];
            #pragma unroll
            for (int nf = 0; nf < 8; nf++)
                #pragma unroll
                for (int e = 0; e < 4; e++) s[nf][e] = 0.f;

            #pragma unroll
            for (int ks = 0; ks < 4; ks++) {
                #pragma unroll
                for (int nf = 0; nf < 8; nf++) {
                    uint32_t koff = SWZ128((nf * 8 + b_r) * 128 + ks * 32 + b_cb);
                    uint32_t kbh[2], kbl[2];
                    ldsm_x2(kbh, kb + koff);
                    ldsm_x2(kbl, kb + 8192 + koff);
                    mma16816(s[nf], rah[ks], kbh);
                    mma16816(s[nf], rah[ks], kbl);
                    mma16816(s[nf], ral[ks], kbh);
                }
            }
            // scale + causal mask
            #pragma unroll
            for (int nf = 0; nf < 8; nf++) {
                int col = kt * 64 + nf * 8 + (lane & 3) * 2;
                s[nf][0] = (col     > rA)     ? -1e30f : s[nf][0] * 0.125f;
                s[nf][1] = (col + 1 > rA)     ? -1e30f : s[nf][1] * 0.125f;
                s[nf][2] = (col     > rA + 8) ? -1e30f : s[nf][2] * 0.125f;
                s[nf][3] = (col + 1 > rA + 8) ? -1e30f : s[nf][3] * 0.125f;
            }
            // online softmax (rows rA and rA+8)
            float tmA = -1e30f, tmB = -1e30f;
            #pragma unroll
            for (int nf = 0; nf < 8; nf++) {
                tmA = fmaxf(tmA, fmaxf(s[nf][0], s[nf][1]));
                tmB = fmaxf(tmB, fmaxf(s[nf][2], s[nf][3]));
            }
            tmA = fmaxf(tmA, __shfl_xor_sync(0xffffffffu, tmA, 1));
            tmA = fmaxf(tmA, __shfl_xor_sync(0xffffffffu, tmA, 2));
            tmB = fmaxf(tmB, __shfl_xor_sync(0xffffffffu, tmB, 1));
            tmB = fmaxf(tmB, __shfl_xor_sync(0xffffffffu, tmB, 2));
            float mnA = fmaxf(mrow[0], tmA), mnB = fmaxf(mrow[1], tmB);
            float cA = __expf(mrow[0] - mnA), cB = __expf(mrow[1] - mnB);
            float lsA = 0.f, lsB = 0.f;
            #pragma unroll
            for (int nf = 0; nf < 8; nf++) {
                s[nf][0] = __expf(s[nf][0] - mnA);
                s[nf][1] = __expf(s[nf][1] - mnA);
                s[nf][2] = __expf(s[nf][2] - mnB);
                s[nf][3] = __expf(s[nf][3] - mnB);
                lsA += s[nf][0] + s[nf][1];
                lsB += s[nf][2] + s[nf][3];
            }
            lsA += __shfl_xor_sync(0xffffffffu, lsA, 1);
            lsA += __shfl_xor_sync(0xffffffffu, lsA, 2);
            lsB += __shfl_xor_sync(0xffffffffu, lsB, 1);
            lsB += __shfl_xor_sync(0xffffffffu, lsB, 2);
            lrow[0] = lrow[0] * cA + lsA; mrow[0] = mnA;
            lrow[1] = lrow[1] * cB + lsB; mrow[1] = mnB;
            #pragma unroll
            for (int nf = 0; nf < 8; nf++) {
                o[nf][0] *= cA; o[nf][1] *= cA;
                o[nf][2] *= cB; o[nf][3] *= cB;
            }
            // P @ V (P split hi/lo; V hi/lo)
            #pragma unroll
            for (int ks = 0; ks < 4; ks++) {
                uint32_t phi[4], plo[4];
                {
                    float* f0 = s[2 * ks];
                    float* f1 = s[2 * ks + 1];
                    phi[0] = packbf2(f0[0], f0[1]);
                    phi[1] = packbf2(f0[2], f0[3]);
                    phi[2] = packbf2(f1[0], f1[1]);
                    phi[3] = packbf2(f1[2], f1[3]);
                    __nv_bfloat162* hp;
                    hp = (__nv_bfloat162*)&phi[0];
                    plo[0] = packbf2(f0[0] - __bfloat162float(hp->x), f0[1] - __bfloat162float(hp->y));
                    hp = (__nv_bfloat162*)&phi[1];
                    plo[1] = packbf2(f0[2] - __bfloat162float(hp->x), f0[3] - __bfloat162float(hp->y));
                    hp = (__nv_bfloat162*)&phi[2];
                    plo[2] = packbf2(f1[0] - __bfloat162float(hp->x), f1[1] - __bfloat162float(hp->y));
                    hp = (__nv_bfloat162*)&phi[3];
                    plo[3] = packbf2(f1[2] - __bfloat162float(hp->x), f1[3] - __bfloat162float(hp->y));
                }
                #pragma unroll
                for (int nf = 0; nf < 8; nf++) {
                    uint32_t voff = SWZ128((ks * 16 + b_l) * 128 + nf * 16);
                    uint32_t vbh[2], vbl[2];
                    ldsm_x2t(vbh, kb + 16384 + voff);
                    ldsm_x2t(vbl, kb + 24576 + voff);
                    mma16816(o[nf], phi, vbh);
                    mma16816(o[nf], phi, vbl);
                    mma16816(o[nf], plo, vbh);
                }
            }
        }
        __syncthreads();
    }

    float iA = 1.f / lrow[0], iB = 1.f / lrow[1];
    #pragma unroll
    for (int nf = 0; nf < 8; nf++) {
        int col = nf * 8 + (lane & 3) * 2;
        float v0 = o[nf][0] * iA, v1 = o[nf][1] * iA;
        float v2 = o[nf][2] * iB, v3 = o[nf][3] * iB;
        size_t baseA = (size_t)(b * TSEQ + rA) * EDIM + hoff + col;
        size_t baseB = (size_t)(b * TSEQ + rA + 8) * EDIM + hoff + col;
        __nv_bfloat16 h0 = __float2bfloat16(v0), h1 = __float2bfloat16(v1);
        __nv_bfloat16 h2 = __float2bfloat16(v2), h3 = __float2bfloat16(v3);
        *(__nv_bfloat162*)(Oh + baseA) = __nv_bfloat162(h0, h1);
        *(__nv_bfloat162*)(Oh + baseB) = __nv_bfloat162(h2, h3);
        *(__nv_bfloat162*)(Ol + baseA) =
            __nv_bfloat162(__float2bfloat16(v0 - __bfloat162float(h0)),
                           __float2bfloat16(v1 - __bfloat162float(h1)));
        *(__nv_bfloat162*)(Ol + baseB) =
            __nv_bfloat162(__float2bfloat16(v2 - __bfloat162float(h2)),
                           __float2bfloat16(v3 - __bfloat162float(h3)));
    }
}

// ---------------- launch -----------------------------------------------------
extern "C" void kernel_launch(void* const* d_in, const int* in_sizes, int n_in,
                              void* d_out, int out_size)
{
    const float* x    = (const float*)d_in[0];
    const float* ln1g = (const float*)d_in[1];
    const float* ln1b = (const float*)d_in[2];
    const float* Wq   = (const float*)d_in[3];
    const float* Wk   = (const float*)d_in[4];
    const float* Wv   = (const float*)d_in[5];
    const float* Wo   = (const float*)d_in[6];
    const float* bo   = (const float*)d_in[7];
    const float* ln2g = (const float*)d_in[8];
    const float* ln2b = (const float*)d_in[9];
    const float* W1   = (const float*)d_in[10];
    const float* b1   = (const float*)d_in[11];
    const float* W2   = (const float*)d_in[12];
    const float* b2   = (const float*)d_in[13];
    float* out = (float*)d_out;

    float* x1;
    __nv_bfloat16 *ah, *al, *bh, *bl, *qh, *ql, *kh, *kl, *vh, *vl;
    __nv_bfloat16 *wqh, *wql, *wkh, *wkl, *wvh, *wvl, *woh, *wol, *w1h, *w1l, *w2h, *w2l;
    cudaGetSymbolAddress((void**)&x1,  g_x1);
    cudaGetSymbolAddress((void**)&ah,  g_ah);
    cudaGetSymbolAddress((void**)&al,  g_al);
    cudaGetSymbolAddress((void**)&bh,  g_bh);
    cudaGetSymbolAddress((void**)&bl,  g_bl);
    cudaGetSymbolAddress((void**)&qh,  g_qh);
    cudaGetSymbolAddress((void**)&ql,  g_ql);
    cudaGetSymbolAddress((void**)&kh,  g_kh);
    cudaGetSymbolAddress((void**)&kl,  g_kl);
    cudaGetSymbolAddress((void**)&vh,  g_vh);
    cudaGetSymbolAddress((void**)&vl,  g_vl);
    cudaGetSymbolAddress((void**)&wqh, g_wqh);
    cudaGetSymbolAddress((void**)&wql, g_wql);
    cudaGetSymbolAddress((void**)&wkh, g_wkh);
    cudaGetSymbolAddress((void**)&wkl, g_wkl);
    cudaGetSymbolAddress((void**)&wvh, g_wvh);
    cudaGetSymbolAddress((void**)&wvl, g_wvl);
    cudaGetSymbolAddress((void**)&woh, g_woh);
    cudaGetSymbolAddress((void**)&wol, g_wol);
    cudaGetSymbolAddress((void**)&w1h, g_w1h);
    cudaGetSymbolAddress((void**)&w1l, g_w1l);
    cudaGetSymbolAddress((void**)&w2h, g_w2h);
    cudaGetSymbolAddress((void**)&w2l, g_w2l);

    cudaFuncSetAttribute(gemm_mma, cudaFuncAttributeMaxDynamicSharedMemorySize, G_SMEM_TOTAL);
    cudaFuncSetAttribute(attn_mma, cudaFuncAttributeMaxDynamicSharedMemorySize, AT_SMEM);

    dim3 tb(32, 8);
    tsplit_kernel<<<dim3(EDIM/32, EDIM/32), tb>>>(Wq, wqh, wql, EDIM, EDIM);
    tsplit_kernel<<<dim3(EDIM/32, EDIM/32), tb>>>(Wk, wkh, wkl, EDIM, EDIM);
    tsplit_kernel<<<dim3(EDIM/32, EDIM/32), tb>>>(Wv, wvh, wvl, EDIM, EDIM);
    tsplit_kernel<<<dim3(EDIM/32, EDIM/32), tb>>>(Wo, woh, wol, EDIM, EDIM);
    tsplit_kernel<<<dim3(FDIM/32, EDIM/32), tb>>>(W1, w1h, w1l, EDIM, FDIM);
    tsplit_kernel<<<dim3(EDIM/32, FDIM/32), tb>>>(W2, w2h, w2l, FDIM, EDIM);

    // 1. LN1 -> bf16 split
    ln_split_kernel<<<MTOK, 256>>>(x, ln1g, ln1b, ah, al);

    // 2. Q,K,V (bf16 split outputs)
    dim3 gE(EDIM/128, MTOK/128);
    gemm_mma<<<gE, 256, G_SMEM_TOTAL>>>(ah, al, wqh, wql, nullptr, qh, ql, nullptr, nullptr, 0, EDIM, EDIM);
    gemm_mma<<<gE, 256, G_SMEM_TOTAL>>>(ah, al, wkh, wkl, nullptr, kh, kl, nullptr, nullptr, 0, EDIM, EDIM);
    gemm_mma<<<gE, 256, G_SMEM_TOTAL>>>(ah, al, wvh, wvl, nullptr, vh, vl, nullptr, nullptr, 0, EDIM, EDIM);

    // 3. causal MHA (bf16 split output)
    attn_mma<<<dim3(TSEQ/128, NHEAD, BATCH), 256, AT_SMEM>>>(qh, ql, kh, kl, vh, vl, ah, al);

    // 4. x1 = att @ Wo + bo + x
    gemm_mma<<<gE, 256, G_SMEM_TOTAL>>>(ah, al, woh, wol, x1, nullptr, nullptr, bo, x, 0, EDIM, EDIM);

    // 5. LN2 -> bf16 split
    ln_split_kernel<<<MTOK, 256>>>(x1, ln2g, ln2b, ah, al);

    // 6. hid = relu(h @ W1 + b1) (bf16 split output)
    dim3 gF(FDIM/128, MTOK/128);
    gemm_mma<<<gF, 256, G_SMEM_TOTAL>>>(ah, al, w1h, w1l, nullptr, bh, bl, b1, nullptr, 1, FDIM, EDIM);

    // 7. out = hid @ W2 + b2 + x1
    gemm_mma<<<gE, 256, G_SMEM_TOTAL>>>(bh, bl, w2h, w2l, out, nullptr, nullptr, b2, x1, 0, EDIM, FDIM);
}

// round 5
// speedup vs baseline: 7.9510x; 1.2986x over previous
#include <cuda_runtime.h>
#include <cuda_fp16.h>
#include <cstdint>
#include <cstddef>

// Problem dims
#define BATCH 2
#define TSEQ  2048
#define EDIM  1024
#define FDIM  4096
#define NHEAD 16
#define HDIM  64
#define MTOK  (BATCH*TSEQ)   // 4096 rows

// ---------------- scratch (device globals: allocation-free) ----------------
__device__ float g_x1 [MTOK*EDIM];
__device__ __half g_ah [MTOK*FDIM];
__device__ __half g_al [MTOK*FDIM];
__device__ __half g_bh [MTOK*FDIM];
__device__ __half g_bl [MTOK*FDIM];
__device__ __half g_qh [MTOK*EDIM], g_ql [MTOK*EDIM];
__device__ __half g_kh [MTOK*EDIM], g_kl [MTOK*EDIM];
__device__ __half g_vh [MTOK*EDIM];
__device__ __half g_wqh[EDIM*EDIM];
__device__ __half g_wkh[EDIM*EDIM];
__device__ __half g_wvh[EDIM*EDIM];
__device__ __half g_woh[EDIM*EDIM];
__device__ __half g_w1h[FDIM*EDIM];
__device__ __half g_w2h[EDIM*FDIM];

// ---------------- PTX helpers (sm_80-compatible only) ----------------
__device__ __forceinline__ uint32_t smem_u32(const void* p) {
    uint32_t a;
    asm("{ .reg .u64 t; cvta.to.shared.u64 t, %1; cvt.u32.u64 %0, t; }" : "=r"(a) : "l"(p));
    return a;
}
#define SWZ128(o) ((o) ^ ((((uint32_t)(o)) >> 3) & 0x70u))

#define CP_ASYNC16(dst, src) \
    asm volatile("cp.async.cg.shared.global [%0], [%1], 16;" :: "r"(dst), "l"(src) : "memory")
#define CP_COMMIT()  asm volatile("cp.async.commit_group;" ::: "memory")
#define CP_WAIT(n)   asm volatile("cp.async.wait_group %0;" :: "n"(n) : "memory")

__device__ __forceinline__ void ldsm_x4(uint32_t* r, uint32_t addr) {
    asm volatile("ldmatrix.sync.aligned.m8n8.x4.shared.b16 {%0,%1,%2,%3}, [%4];"
                 : "=r"(r[0]), "=r"(r[1]), "=r"(r[2]), "=r"(r[3]) : "r"(addr));
}
__device__ __forceinline__ void ldsm_x2(uint32_t* r, uint32_t addr) {
    asm volatile("ldmatrix.sync.aligned.m8n8.x2.shared.b16 {%0,%1}, [%2];"
                 : "=r"(r[0]), "=r"(r[1]) : "r"(addr));
}
__device__ __forceinline__ void ldsm_x2t(uint32_t* r, uint32_t addr) {
    asm volatile("ldmatrix.sync.aligned.m8n8.x2.trans.shared.b16 {%0,%1}, [%2];"
                 : "=r"(r[0]), "=r"(r[1]) : "r"(addr));
}
__device__ __forceinline__ void mma16816(float* c, const uint32_t* a, const uint32_t* b) {
    asm volatile("mma.sync.aligned.m16n8k16.row.col.f32.f16.f16.f32 "
                 "{%0,%1,%2,%3}, {%4,%5,%6,%7}, {%8,%9}, {%0,%1,%2,%3};"
                 : "+f"(c[0]), "+f"(c[1]), "+f"(c[2]), "+f"(c[3])
                 : "r"(a[0]), "r"(a[1]), "r"(a[2]), "r"(a[3]),
                   "r"(b[0]), "r"(b[1]));
}
__device__ __forceinline__ uint32_t packh2(float a, float b) {
    __half2 t = __floats2half2_rn(a, b);
    return *(uint32_t*)&t;
}

// ---------------- fused LayerNorm -> fp16 hi/lo split ----------------
__global__ __launch_bounds__(256)
void ln_split_kernel(const float* __restrict__ x, const float* __restrict__ g,
                     const float* __restrict__ b, __half* __restrict__ yh,
                     __half* __restrict__ yl)
{
    __shared__ float red[8];
    int row = blockIdx.x;
    int t = threadIdx.x;
    const float4* xr = (const float4*)(x + (size_t)row * EDIM);
    float4 v = xr[t];
    float s = v.x + v.y + v.z + v.w;
    #pragma unroll
    for (int o = 16; o > 0; o >>= 1) s += __shfl_xor_sync(0xffffffffu, s, o);
    if ((t & 31) == 0) red[t >> 5] = s;
    __syncthreads();
    float tot = 0.f;
    #pragma unroll
    for (int i = 0; i < 8; i++) tot += red[i];
    float mean = tot * (1.0f / EDIM);
    float dx = v.x - mean, dy = v.y - mean, dz = v.z - mean, dw = v.w - mean;
    float s2 = dx*dx + dy*dy + dz*dz + dw*dw;
    __syncthreads();
    #pragma unroll
    for (int o = 16; o > 0; o >>= 1) s2 += __shfl_xor_sync(0xffffffffu, s2, o);
    if ((t & 31) == 0) red[t >> 5] = s2;
    __syncthreads();
    float tot2 = 0.f;
    #pragma unroll
    for (int i = 0; i < 8; i++) tot2 += red[i];
    float r = rsqrtf(tot2 * (1.0f / EDIM) + 1e-5f);
    float4 g4 = ((const float4*)g)[t];
    float4 b4 = ((const float4*)b)[t];
    float o0 = dx * r * g4.x + b4.x;
    float o1 = dy * r * g4.y + b4.y;
    float o2 = dz * r * g4.z + b4.z;
    float o3 = dw * r * g4.w + b4.w;
    __half h0 = __float2half_rn(o0), h1 = __float2half_rn(o1);
    __half h2 = __float2half_rn(o2), h3 = __float2half_rn(o3);
    size_t base = (size_t)row * EDIM + t * 4;
    *(__half2*)(yh + base)     = __half2(h0, h1);
    *(__half2*)(yh + base + 2) = __half2(h2, h3);
    *(__half2*)(yl + base) =
        __half2(__float2half_rn(o0 - __half2float(h0)),
                __float2half_rn(o1 - __half2float(h1)));
    *(__half2*)(yl + base + 2) =
        __half2(__float2half_rn(o2 - __half2float(h2)),
                __float2half_rn(o3 - __half2float(h3)));
}

// ---------------- weight transpose: W[K,N] -> T[N,K] fp16 (hi only) ---------
__global__ __launch_bounds__(256)
void wsplit_kernel(const float* __restrict__ W, __half* __restrict__ Th,
                   int K, int N)
{
    __shared__ float tile[32][33];
    int bx = blockIdx.x * 32;   // N
    int by = blockIdx.y * 32;   // K
    int tx = threadIdx.x, ty = threadIdx.y;
    #pragma unroll
    for (int j = 0; j < 32; j += 8)
        tile[ty + j][tx] = W[(size_t)(by + ty + j) * N + bx + tx];
    __syncthreads();
    #pragma unroll
    for (int j = 0; j < 32; j += 8) {
        float v = tile[tx][ty + j];
        Th[(size_t)(bx + ty + j) * K + by + tx] = __float2half_rn(v);
    }
}

// ---------------- mma.sync fp16 2-term GEMM ----------------------------------
// C[M,N] = (Ah+Al)[M,K] @ Bh[N,K]^T. Tile 128x128, K-chunk 64, 8 warps 2x4.
#define G_TILE_B     16384
#define G_STAGE_B    (3*G_TILE_B)
#define G_SMEM_TOTAL (2*G_STAGE_B)

__global__ __launch_bounds__(256, 1)
void gemm_mma(const __half* __restrict__ Ah, const __half* __restrict__ Al,
              const __half* __restrict__ Bh,
              float* __restrict__ C, __half* __restrict__ Oh,
              __half* __restrict__ Ol, const float* __restrict__ bias,
              const float* __restrict__ resid, int relu, int N, int K)
{
    extern __shared__ __align__(1024) char smem[];
    const uint32_t sb = smem_u32(smem);
    const int tid  = threadIdx.x;
    const int wid  = tid >> 5, lane = tid & 31;
    const int wm   = wid >> 2;
    const int wn   = wid & 3;
    const int bm = blockIdx.y, bn = blockIdx.x;

    const size_t arow0 = (size_t)bm * 128;
    const size_t brow0 = (size_t)bn * 128;

    auto load_stage = [&](int s, int k0) {
        uint32_t base = sb + s * G_STAGE_B;
        #pragma unroll
        for (int it = 0; it < 12; it++) {
            int c   = tid + it * 256;
            int tl  = c >> 10;          // 0..2
            int idx = c & 1023;
            int r   = idx >> 3;
            int c16 = idx & 7;
            uint32_t dst = base + tl * G_TILE_B + SWZ128(r * 128 + c16 * 16);
            const __half* src;
            if      (tl == 0) src = Ah + (arow0 + r) * K + k0 + c16 * 8;
            else if (tl == 1) src = Al + (arow0 + r) * K + k0 + c16 * 8;
            else              src = Bh + (brow0 + r) * K + k0 + c16 * 8;
            CP_ASYNC16(dst, src);
        }
        CP_COMMIT();
    };

    float acc[4][4][4];
    #pragma unroll
    for (int mf = 0; mf < 4; mf++)
        #pragma unroll
        for (int nf = 0; nf < 4; nf++)
            #pragma unroll
            for (int e = 0; e < 4; e++) acc[mf][nf][e] = 0.f;

    const int nch = K >> 6;
    load_stage(0, 0);

    const int a_r  = (lane & 7) + ((lane >> 3) & 1) * 8;
    const int a_cb = (lane >> 4) * 16;
    const int b_l  = lane & 15;
    const int b_r  = b_l & 7;
    const int b_cb = ((b_l >> 3) & 1) * 16;

    for (int i = 0; i < nch; i++) {
        if (i + 1 < nch) { load_stage((i + 1) & 1, (i + 1) << 6); CP_WAIT(1); }
        else             { CP_WAIT(0); }
        __syncthreads();

        uint32_t tAh = sb + (i & 1) * G_STAGE_B;
        uint32_t tAl = tAh + G_TILE_B;
        uint32_t tBh = tAh + 2 * G_TILE_B;

        #pragma unroll
        for (int ks = 0; ks < 4; ks++) {
            uint32_t rah[4][4], ral[4][4], rbh[4][2];
            #pragma unroll
            for (int mf = 0; mf < 4; mf++) {
                uint32_t off = SWZ128((wm * 64 + mf * 16 + a_r) * 128 + ks * 32 + a_cb);
                ldsm_x4(rah[mf], tAh + off);
                ldsm_x4(ral[mf], tAl + off);
            }
            #pragma unroll
            for (int nf = 0; nf < 4; nf++) {
                uint32_t off = SWZ128((wn * 32 + nf * 8 + b_r) * 128 + ks * 32 + b_cb);
                ldsm_x2(rbh[nf], tBh + off);
            }
            #pragma unroll
            for (int mf = 0; mf < 4; mf++)
                #pragma unroll
                for (int nf = 0; nf < 4; nf++) {
                    mma16816(acc[mf][nf], rah[mf], rbh[nf]);
                    mma16816(acc[mf][nf], ral[mf], rbh[nf]);
                }
        }
        __syncthreads();
    }

    int rbase = bm * 128 + wm * 64 + (lane >> 2);
    int cbase = bn * 128 + wn * 32 + (lane & 3) * 2;
    #pragma unroll
    for (int mf = 0; mf < 4; mf++) {
        #pragma unroll
        for (int half = 0; half < 2; half++) {
            int row = rbase + mf * 16 + half * 8;
            #pragma unroll
            for (int nf = 0; nf < 4; nf++) {
                int col = cbase + nf * 8;
                float ox = acc[mf][nf][half * 2 + 0];
                float oy = acc[mf][nf][half * 2 + 1];
                if (bias) {
                    float2 bb = *(const float2*)(bias + col);
                    ox += bb.x; oy += bb.y;
                }
                if (relu) { ox = fmaxf(ox, 0.f); oy = fmaxf(oy, 0.f); }
                if (resid) {
                    float2 rr = *(const float2*)(resid + (size_t)row * N + col);
                    ox += rr.x; oy += rr.y;
                }
                if (C) {
                    float2 o2; o2.x = ox; o2.y = oy;
                    *(float2*)(C + (size_t)row * N + col) = o2;
                }
                if (Oh) {
                    __half hx = __float2half_rn(ox);
                    __half hy = __float2half_rn(oy);
                    *(__half2*)(Oh + (size_t)row * N + col) = __half2(hx, hy);
                    if (Ol)
                        *(__half2*)(Ol + (size_t)row * N + col) =
                            __half2(__float2half_rn(ox - __half2float(hx)),
                                    __float2half_rn(oy - __half2float(hy)));
                }
            }
        }
    }
}

// ---------------- tensor-core causal flash attention --------------------------
// 128 queries/block, 8 warps (16 q rows each), 64-key tiles double-buffered.
// QK^T: 3-term fp16 (Q exact, K exact-ish). PV: 2-term (P exact, V rounded).
// smem: Qh[0,16K) Ql[16K,32K); stage s at 32K+s*24K: Kh+0 Kl+8K Vh+16K.
#define AT_STAGE (3*8192)
#define AT_SMEM  (32768 + 2*AT_STAGE)

__global__ __launch_bounds__(256, 1)
void attn_mma(const __half* __restrict__ Qh, const __half* __restrict__ Ql,
              const __half* __restrict__ Kh, const __half* __restrict__ Kl,
              const __half* __restrict__ Vh,
              __half* __restrict__ Oh, __half* __restrict__ Ol)
{
    extern __shared__ __align__(1024) char smem[];
    const uint32_t sb = smem_u32(smem);
    const int tid = threadIdx.x, wid = tid >> 5, lane = tid & 31;
    const int qt = blockIdx.x, h = blockIdx.y, b = blockIdx.z;
    const int q0 = qt * 128;
    const size_t hoff = (size_t)h * HDIM;

    #pragma unroll
    for (int it = 0; it < 8; it++) {
        int idx = tid + it * 256;
        int tl = idx >> 10, r = (idx >> 3) & 127, c16 = idx & 7;
        uint32_t dst = sb + tl * 16384 + SWZ128(r * 128 + c16 * 16);
        const __half* src =
            (tl ? Ql : Qh) + (size_t)(b * TSEQ + q0 + r) * EDIM + hoff + c16 * 8;
        CP_ASYNC16(dst, src);
    }
    auto load_kv = [&](int s, int kbase) {
        uint32_t base = sb + 32768 + s * AT_STAGE;
        #pragma unroll
        for (int it = 0; it < 6; it++) {
            int idx = tid + it * 256;
            int tl = idx >> 9, r = (idx >> 3) & 63, c16 = idx & 7;
            uint32_t dst = base + tl * 8192 + SWZ128(r * 128 + c16 * 16);
            size_t go = (size_t)(b * TSEQ + kbase + r) * EDIM + hoff + c16 * 8;
            const __half* p;
            if (tl == 0) p = Kh + go; else if (tl == 1) p = Kl + go;
            else p = Vh + go;
            CP_ASYNC16(dst, p);
        }
        CP_COMMIT();
    };
    load_kv(0, 0);

    const int a_r  = (lane & 7) + ((lane >> 3) & 1) * 8;
    const int a_cb = (lane >> 4) * 16;
    const int b_l  = lane & 15;
    const int b_r  = b_l & 7;
    const int b_cb = ((b_l >> 3) & 1) * 16;
    const int rA   = q0 + wid * 16 + (lane >> 2);
    const int wrowmax = q0 + wid * 16 + 15;

    float mrow[2] = {-1e30f, -1e30f};
    float lrow[2] = {0.f, 0.f};
    float o[8][4];
    #pragma unroll
    for (int nf = 0; nf < 8; nf++)
        #pragma unroll
        for (int e = 0; e < 4; e++) o[nf][e] = 0.f;
    uint32_t rah[4][4], ral[4][4];

    const int nkt = (q0 + 128) / 64;
    for (int kt = 0; kt < nkt; kt++) {
        if (kt + 1 < nkt) { load_kv((kt + 1) & 1, (kt + 1) * 64); CP_WAIT(1); }
        else              { CP_WAIT(0); }
        __syncthreads();
        if (kt == 0) {
            #pragma unroll
            for (int ks = 0; ks < 4; ks++) {
                uint32_t off = SWZ128((wid * 16 + a_r) * 128 + ks * 32 + a_cb);
                ldsm_x4(rah[ks], sb + off);
                ldsm_x4(ral[ks], sb + 16384 + off);
            }
        }
        if (kt * 64 <= wrowmax) {
            uint32_t kb = sb + 32768 + (kt & 1) * AT_STAGE;
            float s[8][4];
            #pragma unroll
            for (int nf = 0; nf < 8; nf++)
                #pragma unroll
                for (int e = 0; e < 4; e++) s[nf][e] = 0.f;

            #pragma unroll
            for (int ks = 0; ks < 4; ks++) {
                #pragma unroll
                for (int nf = 0; nf < 8; nf++) {
                    uint32_t koff = SWZ128((nf * 8 + b_r) * 128 + ks * 32 + b_cb);
                    uint32_t kbh[2], kbl[2];
                    ldsm_x2(kbh, kb + koff);
                    ldsm_x2(kbl, kb + 8192 + koff);
                    mma16816(s[nf], rah[ks], kbh);
                    mma16816(s[nf], rah[ks], kbl);
                    mma16816(s[nf], ral[ks], kbh);
                }
            }
            #pragma unroll
            for (int nf = 0; nf < 8; nf++) {
                int col = kt * 64 + nf * 8 + (lane & 3) * 2;
                s[nf][0] = (col     > rA)     ? -1e30f : s[nf][0] * 0.125f;
                s[nf][1] = (col + 1 > rA)     ? -1e30f : s[nf][1] * 0.125f;
                s[nf][2] = (col     > rA + 8) ? -1e30f : s[nf][2] * 0.125f;
                s[nf][3] = (col + 1 > rA + 8) ? -1e30f : s[nf][3] * 0.125f;
            }
            float tmA = -1e30f, tmB = -1e30f;
            #pragma unroll
            for (int nf = 0; nf < 8; nf++) {
                tmA = fmaxf(tmA, fmaxf(s[nf][0], s[nf][1]));
                tmB = fmaxf(tmB, fmaxf(s[nf][2], s[nf][3]));
            }
            tmA = fmaxf(tmA, __shfl_xor_sync(0xffffffffu, tmA, 1));
            tmA = fmaxf(tmA, __shfl_xor_sync(0xffffffffu, tmA, 2));
            tmB = fmaxf(tmB, __shfl_xor_sync(0xffffffffu, tmB, 1));
            tmB = fmaxf(tmB, __shfl_xor_sync(0xffffffffu, tmB, 2));
            float mnA = fmaxf(mrow[0], tmA), mnB = fmaxf(mrow[1], tmB);
            float cA = __expf(mrow[0] - mnA), cB = __expf(mrow[1] - mnB);
            float lsA = 0.f, lsB = 0.f;
            #pragma unroll
            for (int nf = 0; nf < 8; nf++) {
                s[nf][0] = __expf(s[nf][0] - mnA);
                s[nf][1] = __expf(s[nf][1] - mnA);
                s[nf][2] = __expf(s[nf][2] - mnB);
                s[nf][3] = __expf(s[nf][3] - mnB);
                lsA += s[nf][0] + s[nf][1];
                lsB += s[nf][2] + s[nf][3];
            }
            lsA += __shfl_xor_sync(0xffffffffu, lsA, 1);
            lsA += __shfl_xor_sync(0xffffffffu, lsA, 2);
            lsB += __shfl_xor_sync(0xffffffffu, lsB, 1);
            lsB += __shfl_xor_sync(0xffffffffu, lsB, 2);
            lrow[0] = lrow[0] * cA + lsA; mrow[0] = mnA;
            lrow[1] = lrow[1] * cB + lsB; mrow[1] = mnB;
            #pragma unroll
            for (int nf = 0; nf < 8; nf++) {
                o[nf][0] *= cA; o[nf][1] *= cA;
                o[nf][2] *= cB; o[nf][3] *= cB;
            }
            #pragma unroll
            for (int ks = 0; ks < 4; ks++) {
                uint32_t phi[4], plo[4];
                {
                    float* f0 = s[2 * ks];
                    float* f1 = s[2 * ks + 1];
                    phi[0] = packh2(f0[0], f0[1]);
                    phi[1] = packh2(f0[2], f0[3]);
                    phi[2] = packh2(f1[0], f1[1]);
                    phi[3] = packh2(f1[2], f1[3]);
                    __half2* hp;
                    hp = (__half2*)&phi[0];
                    plo[0] = packh2(f0[0] - __half2float(hp->x), f0[1] - __half2float(hp->y));
                    hp = (__half2*)&phi[1];
                    plo[1] = packh2(f0[2] - __half2float(hp->x), f0[3] - __half2float(hp->y));
                    hp = (__half2*)&phi[2];
                    plo[2] = packh2(f1[0] - __half2float(hp->x), f1[1] - __half2float(hp->y));
                    hp = (__half2*)&phi[3];
                    plo[3] = packh2(f1[2] - __half2float(hp->x), f1[3] - __half2float(hp->y));
                }
                #pragma unroll
                for (int nf = 0; nf < 8; nf++) {
                    uint32_t voff = SWZ128((ks * 16 + b_l) * 128 + nf * 16);
                    uint32_t vbh[2];
                    ldsm_x2t(vbh, kb + 16384 + voff);
                    mma16816(o[nf], phi, vbh);
                    mma16816(o[nf], plo, vbh);
                }
            }
        }
        __syncthreads();
    }

    float iA = 1.f / lrow[0], iB = 1.f / lrow[1];
    #pragma unroll
    for (int nf = 0; nf < 8; nf++) {
        int col = nf * 8 + (lane & 3) * 2;
        float v0 = o[nf][0] * iA, v1 = o[nf][1] * iA;
        float v2 = o[nf][2] * iB, v3 = o[nf][3] * iB;
        size_t baseA = (size_t)(b * TSEQ + rA) * EDIM + hoff + col;
        size_t baseB = (size_t)(b * TSEQ + rA + 8) * EDIM + hoff + col;
        __half h0 = __float2half_rn(v0), h1 = __float2half_rn(v1);
        __half h2 = __float2half_rn(v2), h3 = __float2half_rn(v3);
        *(__half2*)(Oh + baseA) = __half2(h0, h1);
        *(__half2*)(Oh + baseB) = __half2(h2, h3);
        *(__half2*)(Ol + baseA) =
            __half2(__float2half_rn(v0 - __half2float(h0)),
                    __float2half_rn(v1 - __half2float(h1)));
        *(__half2*)(Ol + baseB) =
            __half2(__float2half_rn(v2 - __half2float(h2)),
                    __float2half_rn(v3 - __half2float(h3)));
    }
}

// ---------------- launch -----------------------------------------------------
extern "C" void kernel_launch(void* const* d_in, const int* in_sizes, int n_in,
                              void* d_out, int out_size)
{
    const float* x    = (const float*)d_in[0];
    const float* ln1g = (const float*)d_in[1];
    const float* ln1b = (const float*)d_in[2];
    const float* Wq   = (const float*)d_in[3];
    const float* Wk   = (const float*)d_in[4];
    const float* Wv   = (const float*)d_in[5];
    const float* Wo   = (const float*)d_in[6];
    const float* bo   = (const float*)d_in[7];
    const float* ln2g = (const float*)d_in[8];
    const float* ln2b = (const float*)d_in[9];
    const float* W1   = (const float*)d_in[10];
    const float* b1   = (const float*)d_in[11];
    const float* W2   = (const float*)d_in[12];
    const float* b2   = (const float*)d_in[13];
    float* out = (float*)d_out;

    float* x1;
    __half *ah, *al, *bh, *bl, *qh, *ql, *kh, *kl, *vh;
    __half *wqh, *wkh, *wvh, *woh, *w1h, *w2h;
    cudaGetSymbolAddress((void**)&x1,  g_x1);
    cudaGetSymbolAddress((void**)&ah,  g_ah);
    cudaGetSymbolAddress((void**)&al,  g_al);
    cudaGetSymbolAddress((void**)&bh,  g_bh);
    cudaGetSymbolAddress((void**)&bl,  g_bl);
    cudaGetSymbolAddress((void**)&qh,  g_qh);
    cudaGetSymbolAddress((void**)&ql,  g_ql);
    cudaGetSymbolAddress((void**)&kh,  g_kh);
    cudaGetSymbolAddress((void**)&kl,  g_kl);
    cudaGetSymbolAddress((void**)&vh,  g_vh);
    cudaGetSymbolAddress((void**)&wqh, g_wqh);
    cudaGetSymbolAddress((void**)&wkh, g_wkh);
    cudaGetSymbolAddress((void**)&wvh, g_wvh);
    cudaGetSymbolAddress((void**)&woh, g_woh);
    cudaGetSymbolAddress((void**)&w1h, g_w1h);
    cudaGetSymbolAddress((void**)&w2h, g_w2h);

    cudaFuncSetAttribute(gemm_mma, cudaFuncAttributeMaxDynamicSharedMemorySize, G_SMEM_TOTAL);
    cudaFuncSetAttribute(attn_mma, cudaFuncAttributeMaxDynamicSharedMemorySize, AT_SMEM);

    dim3 tb(32, 8);
    wsplit_kernel<<<dim3(EDIM/32, EDIM/32), tb>>>(Wq, wqh, EDIM, EDIM);
    wsplit_kernel<<<dim3(EDIM/32, EDIM/32), tb>>>(Wk, wkh, EDIM, EDIM);
    wsplit_kernel<<<dim3(EDIM/32, EDIM/32), tb>>>(Wv, wvh, EDIM, EDIM);
    wsplit_kernel<<<dim3(EDIM/32, EDIM/32), tb>>>(Wo, woh, EDIM, EDIM);
    wsplit_kernel<<<dim3(FDIM/32, EDIM/32), tb>>>(W1, w1h, EDIM, FDIM);
    wsplit_kernel<<<dim3(EDIM/32, FDIM/32), tb>>>(W2, w2h, FDIM, EDIM);

    // 1. LN1 -> fp16 split
    ln_split_kernel<<<MTOK, 256>>>(x, ln1g, ln1b, ah, al);

    // 2. Q,K,V
    dim3 gE(EDIM/128, MTOK/128);
    gemm_mma<<<gE, 256, G_SMEM_TOTAL>>>(ah, al, wqh, nullptr, qh, ql, nullptr, nullptr, 0, EDIM, EDIM);
    gemm_mma<<<gE, 256, G_SMEM_TOTAL>>>(ah, al, wkh, nullptr, kh, kl, nullptr, nullptr, 0, EDIM, EDIM);
    gemm_mma<<<gE, 256, G_SMEM_TOTAL>>>(ah, al, wvh, nullptr, vh, nullptr, nullptr, nullptr, 0, EDIM, EDIM);

    // 3. causal MHA (fp16 split output)
    attn_mma<<<dim3(TSEQ/128, NHEAD, BATCH), 256, AT_SMEM>>>(qh, ql, kh, kl, vh, ah, al);

    // 4. x1 = att @ Wo + bo + x
    gemm_mma<<<gE, 256, G_SMEM_TOTAL>>>(ah, al, woh, x1, nullptr, nullptr, bo, x, 0, EDIM, EDIM);

    // 5. LN2 -> fp16 split
    ln_split_kernel<<<MTOK, 256>>>(x1, ln2g, ln2b, ah, al);

    // 6. hid = relu(h @ W1 + b1)
    dim3 gF(FDIM/128, MTOK/128);
    gemm_mma<<<gF, 256, G_SMEM_TOTAL>>>(ah, al, w1h, nullptr, bh, bl, b1, nullptr, 1, FDIM, EDIM);

    // 7. out = hid @ W2 + b2 + x1
    gemm_mma<<<gE, 256, G_SMEM_TOTAL>>>(bh, bl, w2h, out, nullptr, nullptr, b2, x1, 0, EDIM, FDIM);
}

// round 6
// speedup vs baseline: 10.1566x; 1.2774x over previous
#include <cuda_runtime.h>
#include <cuda_fp16.h>
#include <cstdint>
#include <cstddef>

// Problem dims
#define BATCH 2
#define TSEQ  2048
#define EDIM  1024
#define FDIM  4096
#define NHEAD 16
#define HDIM  64
#define MTOK  (BATCH*TSEQ)   // 4096 rows

// ---------------- scratch (device globals: allocation-free) ----------------
__device__ float g_x1 [MTOK*EDIM];
__device__ __half g_ah [MTOK*FDIM];
__device__ __half g_al [MTOK*EDIM];
__device__ __half g_bh [MTOK*FDIM];
__device__ __half g_qh [MTOK*EDIM], g_ql [MTOK*EDIM];
__device__ __half g_kh [MTOK*EDIM], g_kl [MTOK*EDIM];
__device__ __half g_vh [MTOK*EDIM];
__device__ __half g_wqh[EDIM*EDIM];
__device__ __half g_wkh[EDIM*EDIM];
__device__ __half g_wvh[EDIM*EDIM];
__device__ __half g_woh[EDIM*EDIM];
__device__ __half g_w1h[FDIM*EDIM];
__device__ __half g_w2h[EDIM*FDIM];

// ---------------- PTX helpers (sm_80-compatible only) ----------------
__device__ __forceinline__ uint32_t smem_u32(const void* p) {
    uint32_t a;
    asm("{ .reg .u64 t; cvta.to.shared.u64 t, %1; cvt.u32.u64 %0, t; }" : "=r"(a) : "l"(p));
    return a;
}
#define SWZ128(o) ((o) ^ ((((uint32_t)(o)) >> 3) & 0x70u))

#define CP_ASYNC16(dst, src) \
    asm volatile("cp.async.cg.shared.global [%0], [%1], 16;" :: "r"(dst), "l"(src) : "memory")
#define CP_COMMIT()  asm volatile("cp.async.commit_group;" ::: "memory")
#define CP_WAIT(n)   asm volatile("cp.async.wait_group %0;" :: "n"(n) : "memory")

__device__ __forceinline__ void ldsm_x4(uint32_t* r, uint32_t addr) {
    asm volatile("ldmatrix.sync.aligned.m8n8.x4.shared.b16 {%0,%1,%2,%3}, [%4];"
                 : "=r"(r[0]), "=r"(r[1]), "=r"(r[2]), "=r"(r[3]) : "r"(addr));
}
__device__ __forceinline__ void ldsm_x2(uint32_t* r, uint32_t addr) {
    asm volatile("ldmatrix.sync.aligned.m8n8.x2.shared.b16 {%0,%1}, [%2];"
                 : "=r"(r[0]), "=r"(r[1]) : "r"(addr));
}
__device__ __forceinline__ void ldsm_x2t(uint32_t* r, uint32_t addr) {
    asm volatile("ldmatrix.sync.aligned.m8n8.x2.trans.shared.b16 {%0,%1}, [%2];"
                 : "=r"(r[0]), "=r"(r[1]) : "r"(addr));
}
__device__ __forceinline__ void mma16816(float* c, const uint32_t* a, const uint32_t* b) {
    asm volatile("mma.sync.aligned.m16n8k16.row.col.f32.f16.f16.f32 "
                 "{%0,%1,%2,%3}, {%4,%5,%6,%7}, {%8,%9}, {%0,%1,%2,%3};"
                 : "+f"(c[0]), "+f"(c[1]), "+f"(c[2]), "+f"(c[3])
                 : "r"(a[0]), "r"(a[1]), "r"(a[2]), "r"(a[3]),
                   "r"(b[0]), "r"(b[1]));
}
__device__ __forceinline__ uint32_t packh2(float a, float b) {
    __half2 t = __floats2half2_rn(a, b);
    return *(uint32_t*)&t;
}

// ---------------- fused LayerNorm -> fp16 (optional lo split) ----------------
__global__ __launch_bounds__(256)
void ln_split_kernel(const float* __restrict__ x, const float* __restrict__ g,
                     const float* __restrict__ b, __half* __restrict__ yh,
                     __half* __restrict__ yl)
{
    __shared__ float red[8];
    int row = blockIdx.x;
    int t = threadIdx.x;
    const float4* xr = (const float4*)(x + (size_t)row * EDIM);
    float4 v = xr[t];
    float s = v.x + v.y + v.z + v.w;
    #pragma unroll
    for (int o = 16; o > 0; o >>= 1) s += __shfl_xor_sync(0xffffffffu, s, o);
    if ((t & 31) == 0) red[t >> 5] = s;
    __syncthreads();
    float tot = 0.f;
    #pragma unroll
    for (int i = 0; i < 8; i++) tot += red[i];
    float mean = tot * (1.0f / EDIM);
    float dx = v.x - mean, dy = v.y - mean, dz = v.z - mean, dw = v.w - mean;
    float s2 = dx*dx + dy*dy + dz*dz + dw*dw;
    __syncthreads();
    #pragma unroll
    for (int o = 16; o > 0; o >>= 1) s2 += __shfl_xor_sync(0xffffffffu, s2, o);
    if ((t & 31) == 0) red[t >> 5] = s2;
    __syncthreads();
    float tot2 = 0.f;
    #pragma unroll
    for (int i = 0; i < 8; i++) tot2 += red[i];
    float r = rsqrtf(tot2 * (1.0f / EDIM) + 1e-5f);
    float4 g4 = ((const float4*)g)[t];
    float4 b4 = ((const float4*)b)[t];
    float o0 = dx * r * g4.x + b4.x;
    float o1 = dy * r * g4.y + b4.y;
    float o2 = dz * r * g4.z + b4.z;
    float o3 = dw * r * g4.w + b4.w;
    __half h0 = __float2half_rn(o0), h1 = __float2half_rn(o1);
    __half h2 = __float2half_rn(o2), h3 = __float2half_rn(o3);
    size_t base = (size_t)row * EDIM + t * 4;
    *(__half2*)(yh + base)     = __half2(h0, h1);
    *(__half2*)(yh + base + 2) = __half2(h2, h3);
    if (yl) {
        *(__half2*)(yl + base) =
            __half2(__float2half_rn(o0 - __half2float(h0)),
                    __float2half_rn(o1 - __half2float(h1)));
        *(__half2*)(yl + base + 2) =
            __half2(__float2half_rn(o2 - __half2float(h2)),
                    __float2half_rn(o3 - __half2float(h3)));
    }
}

// ---------------- weight transpose: W[K,N] -> T[N,K] fp16 --------------------
__global__ __launch_bounds__(256)
void wsplit_kernel(const float* __restrict__ W, __half* __restrict__ Th,
                   int K, int N)
{
    __shared__ float tile[32][33];
    int bx = blockIdx.x * 32;   // N
    int by = blockIdx.y * 32;   // K
    int tx = threadIdx.x, ty = threadIdx.y;
    #pragma unroll
    for (int j = 0; j < 32; j += 8)
        tile[ty + j][tx] = W[(size_t)(by + ty + j) * N + bx + tx];
    __syncthreads();
    #pragma unroll
    for (int j = 0; j < 32; j += 8) {
        float v = tile[tx][ty + j];
        Th[(size_t)(bx + ty + j) * K + by + tx] = __float2half_rn(v);
    }
}

// ---------------- mma.sync fp16 GEMM (TERMS = 1 or 2 A-planes) ---------------
// C[M,N] = (Ah[+Al])[M,K] @ Bh[N,K]^T. Tile 128x128, K-chunk 64, 8 warps 2x4,
// 3-stage cp.async pipeline.
#define G_TILE_B 16384

template<int TERMS>
__global__ __launch_bounds__(256, 1)
void gemm_mma(const __half* __restrict__ Ah, const __half* __restrict__ Al,
              const __half* __restrict__ Bh,
              float* __restrict__ C, __half* __restrict__ Oh,
              __half* __restrict__ Ol, const float* __restrict__ bias,
              const float* __restrict__ resid, int relu, int N, int K)
{
    const int NT = TERMS + 1;             // tiles per stage
    const uint32_t STAGE_B = NT * G_TILE_B;
    extern __shared__ __align__(1024) char smem[];
    const uint32_t sb = smem_u32(smem);
    const int tid  = threadIdx.x;
    const int wid  = tid >> 5, lane = tid & 31;
    const int wm   = wid >> 2;
    const int wn   = wid & 3;
    const int bm = blockIdx.y, bn = blockIdx.x;

    const size_t arow0 = (size_t)bm * 128;
    const size_t brow0 = (size_t)bn * 128;

    auto load_stage = [&](int s, int k0) {
        uint32_t base = sb + s * STAGE_B;
        #pragma unroll
        for (int it = 0; it < 4 * NT; it++) {
            int c   = tid + it * 256;
            int tl  = c >> 10;
            int idx = c & 1023;
            int r   = idx >> 3;
            int c16 = idx & 7;
            uint32_t dst = base + tl * G_TILE_B + SWZ128(r * 128 + c16 * 16);
            const __half* src;
            if (tl == 0)                       src = Ah + (arow0 + r) * K + k0 + c16 * 8;
            else if (TERMS == 2 && tl == 1)    src = Al + (arow0 + r) * K + k0 + c16 * 8;
            else                               src = Bh + (brow0 + r) * K + k0 + c16 * 8;
            CP_ASYNC16(dst, src);
        }
        CP_COMMIT();
    };

    float acc[4][4][4];
    #pragma unroll
    for (int mf = 0; mf < 4; mf++)
        #pragma unroll
        for (int nf = 0; nf < 4; nf++)
            #pragma unroll
            for (int e = 0; e < 4; e++) acc[mf][nf][e] = 0.f;

    const int nch = K >> 6;
    load_stage(0, 0);
    load_stage(1, 64);

    const int a_r  = (lane & 7) + ((lane >> 3) & 1) * 8;
    const int a_cb = (lane >> 4) * 16;
    const int b_l  = lane & 15;
    const int b_r  = b_l & 7;
    const int b_cb = ((b_l >> 3) & 1) * 16;

    int s3 = 0;   // i % 3
    for (int i = 0; i < nch; i++) {
        if (i + 2 < nch) {
            int sn = s3 + 2; if (sn >= 3) sn -= 3;
            load_stage(sn, (i + 2) << 6);
            CP_WAIT(2);
        } else if (i + 1 < nch) {
            CP_WAIT(1);
        } else {
            CP_WAIT(0);
        }
        __syncthreads();

        uint32_t tAh = sb + s3 * STAGE_B;
        uint32_t tAl = tAh + G_TILE_B;
        uint32_t tBh = tAh + (NT - 1) * G_TILE_B;

        #pragma unroll
        for (int ks = 0; ks < 4; ks++) {
            uint32_t rah[4][4], ral[4][4], rbh[4][2];
            #pragma unroll
            for (int mf = 0; mf < 4; mf++) {
                uint32_t off = SWZ128((wm * 64 + mf * 16 + a_r) * 128 + ks * 32 + a_cb);
                ldsm_x4(rah[mf], tAh + off);
                if (TERMS == 2) ldsm_x4(ral[mf], tAl + off);
            }
            #pragma unroll
            for (int nf = 0; nf < 4; nf++) {
                uint32_t off = SWZ128((wn * 32 + nf * 8 + b_r) * 128 + ks * 32 + b_cb);
                ldsm_x2(rbh[nf], tBh + off);
            }
            #pragma unroll
            for (int mf = 0; mf < 4; mf++)
                #pragma unroll
                for (int nf = 0; nf < 4; nf++) {
                    mma16816(acc[mf][nf], rah[mf], rbh[nf]);
                    if (TERMS == 2) mma16816(acc[mf][nf], ral[mf], rbh[nf]);
                }
        }
        __syncthreads();
        if (++s3 == 3) s3 = 0;
    }

    int rbase = bm * 128 + wm * 64 + (lane >> 2);
    int cbase = bn * 128 + wn * 32 + (lane & 3) * 2;
    #pragma unroll
    for (int mf = 0; mf < 4; mf++) {
        #pragma unroll
        for (int half = 0; half < 2; half++) {
            int row = rbase + mf * 16 + half * 8;
            #pragma unroll
            for (int nf = 0; nf < 4; nf++) {
                int col = cbase + nf * 8;
                float ox = acc[mf][nf][half * 2 + 0];
                float oy = acc[mf][nf][half * 2 + 1];
                if (bias) {
                    float2 bb = *(const float2*)(bias + col);
                    ox += bb.x; oy += bb.y;
                }
                if (relu) { ox = fmaxf(ox, 0.f); oy = fmaxf(oy, 0.f); }
                if (resid) {
                    float2 rr = *(const float2*)(resid + (size_t)row * N + col);
                    ox += rr.x; oy += rr.y;
                }
                if (C) {
                    float2 o2; o2.x = ox; o2.y = oy;
                    *(float2*)(C + (size_t)row * N + col) = o2;
                }
                if (Oh) {
                    __half hx = __float2half_rn(ox);
                    __half hy = __float2half_rn(oy);
                    *(__half2*)(Oh + (size_t)row * N + col) = __half2(hx, hy);
                    if (Ol)
                        *(__half2*)(Ol + (size_t)row * N + col) =
                            __half2(__float2half_rn(ox - __half2float(hx)),
                                    __float2half_rn(oy - __half2float(hy)));
                }
            }
        }
    }
}

// ---------------- tensor-core causal flash attention --------------------------
// 128 queries/block, 8 warps (16 q rows each), 64-key tiles double-buffered.
// QK^T: 3-term fp16. PV: 2-term (P hi/lo, V rounded). Output: fp16 hi only.
#define AT_STAGE (3*8192)
#define AT_SMEM  (32768 + 2*AT_STAGE)

__global__ __launch_bounds__(256, 1)
void attn_mma(const __half* __restrict__ Qh, const __half* __restrict__ Ql,
              const __half* __restrict__ Kh, const __half* __restrict__ Kl,
              const __half* __restrict__ Vh, __half* __restrict__ Oh)
{
    extern __shared__ __align__(1024) char smem[];
    const uint32_t sb = smem_u32(smem);
    const int tid = threadIdx.x, wid = tid >> 5, lane = tid & 31;
    const int qt = blockIdx.x, h = blockIdx.y, b = blockIdx.z;
    const int q0 = qt * 128;
    const size_t hoff = (size_t)h * HDIM;

    #pragma unroll
    for (int it = 0; it < 8; it++) {
        int idx = tid + it * 256;
        int tl = idx >> 10, r = (idx >> 3) & 127, c16 = idx & 7;
        uint32_t dst = sb + tl * 16384 + SWZ128(r * 128 + c16 * 16);
        const __half* src =
            (tl ? Ql : Qh) + (size_t)(b * TSEQ + q0 + r) * EDIM + hoff + c16 * 8;
        CP_ASYNC16(dst, src);
    }
    auto load_kv = [&](int s, int kbase) {
        uint32_t base = sb + 32768 + s * AT_STAGE;
        #pragma unroll
        for (int it = 0; it < 6; it++) {
            int idx = tid + it * 256;
            int tl = idx >> 9, r = (idx >> 3) & 63, c16 = idx & 7;
            uint32_t dst = base + tl * 8192 + SWZ128(r * 128 + c16 * 16);
            size_t go = (size_t)(b * TSEQ + kbase + r) * EDIM + hoff + c16 * 8;
            const __half* p;
            if (tl == 0) p = Kh + go; else if (tl == 1) p = Kl + go;
            else p = Vh + go;
            CP_ASYNC16(dst, p);
        }
        CP_COMMIT();
    };
    load_kv(0, 0);

    const int a_r  = (lane & 7) + ((lane >> 3) & 1) * 8;
    const int a_cb = (lane >> 4) * 16;
    const int b_l  = lane & 15;
    const int b_r  = b_l & 7;
    const int b_cb = ((b_l >> 3) & 1) * 16;
    const int rA   = q0 + wid * 16 + (lane >> 2);
    const int wrowmax = q0 + wid * 16 + 15;

    float mrow[2] = {-1e30f, -1e30f};
    float lrow[2] = {0.f, 0.f};
    float o[8][4];
    #pragma unroll
    for (int nf = 0; nf < 8; nf++)
        #pragma unroll
        for (int e = 0; e < 4; e++) o[nf][e] = 0.f;
    uint32_t rah[4][4], ral[4][4];

    const int nkt = (q0 + 128) / 64;
    for (int kt = 0; kt < nkt; kt++) {
        if (kt + 1 < nkt) { load_kv((kt + 1) & 1, (kt + 1) * 64); CP_WAIT(1); }
        else              { CP_WAIT(0); }
        __syncthreads();
        if (kt == 0) {
            #pragma unroll
            for (int ks = 0; ks < 4; ks++) {
                uint32_t off = SWZ128((wid * 16 + a_r) * 128 + ks * 32 + a_cb);
                ldsm_x4(rah[ks], sb + off);
                ldsm_x4(ral[ks], sb + 16384 + off);
            }
        }
        if (kt * 64 <= wrowmax) {
            uint32_t kb = sb + 32768 + (kt & 1) * AT_STAGE;
            float s[8][4];
            #pragma unroll
            for (int nf = 0; nf < 8; nf++)
                #pragma unroll
                for (int e = 0; e < 4; e++) s[nf][e] = 0.f;

            #pragma unroll
            for (int ks = 0; ks < 4; ks++) {
                #pragma unroll
                for (int nf = 0; nf < 8; nf++) {
                    uint32_t koff = SWZ128((nf * 8 + b_r) * 128 + ks * 32 + b_cb);
                    uint32_t kbh[2], kbl[2];
                    ldsm_x2(kbh, kb + koff);
                    ldsm_x2(kbl, kb + 8192 + koff);
                    mma16816(s[nf], rah[ks], kbh);
                    mma16816(s[nf], rah[ks], kbl);
                    mma16816(s[nf], ral[ks], kbh);
                }
            }
            #pragma unroll
            for (int nf = 0; nf < 8; nf++) {
                int col = kt * 64 + nf * 8 + (lane & 3) * 2;
                s[nf][0] = (col     > rA)     ? -1e30f : s[nf][0] * 0.125f;
                s[nf][1] = (col + 1 > rA)     ? -1e30f : s[nf][1] * 0.125f;
                s[nf][2] = (col     > rA + 8) ? -1e30f : s[nf][2] * 0.125f;
                s[nf][3] = (col + 1 > rA + 8) ? -1e30f : s[nf][3] * 0.125f;
            }
            float tmA = -1e30f, tmB = -1e30f;
            #pragma unroll
            for (int nf = 0; nf < 8; nf++) {
                tmA = fmaxf(tmA, fmaxf(s[nf][0], s[nf][1]));
                tmB = fmaxf(tmB, fmaxf(s[nf][2], s[nf][3]));
            }
            tmA = fmaxf(tmA, __shfl_xor_sync(0xffffffffu, tmA, 1));
            tmA = fmaxf(tmA, __shfl_xor_sync(0xffffffffu, tmA, 2));
            tmB = fmaxf(tmB, __shfl_xor_sync(0xffffffffu, tmB, 1));
            tmB = fmaxf(tmB, __shfl_xor_sync(0xffffffffu, tmB, 2));
            float mnA = fmaxf(mrow[0], tmA), mnB = fmaxf(mrow[1], tmB);
            float cA = __expf(mrow[0] - mnA), cB = __expf(mrow[1] - mnB);
            float lsA = 0.f, lsB = 0.f;
            #pragma unroll
            for (int nf = 0; nf < 8; nf++) {
                s[nf][0] = __expf(s[nf][0] - mnA);
                s[nf][1] = __expf(s[nf][1] - mnA);
                s[nf][2] = __expf(s[nf][2] - mnB);
                s[nf][3] = __expf(s[nf][3] - mnB);
                lsA += s[nf][0] + s[nf][1];
                lsB += s[nf][2] + s[nf][3];
            }
            lsA += __shfl_xor_sync(0xffffffffu, lsA, 1);
            lsA += __shfl_xor_sync(0xffffffffu, lsA, 2);
            lsB += __shfl_xor_sync(0xffffffffu, lsB, 1);
            lsB += __shfl_xor_sync(0xffffffffu, lsB, 2);
            lrow[0] = lrow[0] * cA + lsA; mrow[0] = mnA;
            lrow[1] = lrow[1] * cB + lsB; mrow[1] = mnB;
            #pragma unroll
            for (int nf = 0; nf < 8; nf++) {
                o[nf][0] *= cA; o[nf][1] *= cA;
                o[nf][2] *= cB; o[nf][3] *= cB;
            }
            #pragma unroll
            for (int ks = 0; ks < 4; ks++) {
                uint32_t phi[4], plo[4];
                {
                    float* f0 = s[2 * ks];
                    float* f1 = s[2 * ks + 1];
                    phi[0] = packh2(f0[0], f0[1]);
                    phi[1] = packh2(f0[2], f0[3]);
                    phi[2] = packh2(f1[0], f1[1]);
                    phi[3] = packh2(f1[2], f1[3]);
                    __half2* hp;
                    hp = (__half2*)&phi[0];
                    plo[0] = packh2(f0[0] - __half2float(hp->x), f0[1] - __half2float(hp->y));
                    hp = (__half2*)&phi[1];
                    plo[1] = packh2(f0[2] - __half2float(hp->x), f0[3] - __half2float(hp->y));
                    hp = (__half2*)&phi[2];
                    plo[2] = packh2(f1[0] - __half2float(hp->x), f1[1] - __half2float(hp->y));
                    hp = (__half2*)&phi[3];
                    plo[3] = packh2(f1[2] - __half2float(hp->x), f1[3] - __half2float(hp->y));
                }
                #pragma unroll
                for (int nf = 0; nf < 8; nf++) {
                    uint32_t voff = SWZ128((ks * 16 + b_l) * 128 + nf * 16);
                    uint32_t vbh[2];
                    ldsm_x2t(vbh, kb + 16384 + voff);
                    mma16816(o[nf], phi, vbh);
                    mma16816(o[nf], plo, vbh);
                }
            }
        }
        __syncthreads();
    }

    float iA = 1.f / lrow[0], iB = 1.f / lrow[1];
    #pragma unroll
    for (int nf = 0; nf < 8; nf++) {
        int col = nf * 8 + (lane & 3) * 2;
        float v0 = o[nf][0] * iA, v1 = o[nf][1] * iA;
        float v2 = o[nf][2] * iB, v3 = o[nf][3] * iB;
        size_t baseA = (size_t)(b * TSEQ + rA) * EDIM + hoff + col;
        size_t baseB = (size_t)(b * TSEQ + rA + 8) * EDIM + hoff + col;
        *(__half2*)(Oh + baseA) = __floats2half2_rn(v0, v1);
        *(__half2*)(Oh + baseB) = __floats2half2_rn(v2, v3);
    }
}

// ---------------- launch -----------------------------------------------------
extern "C" void kernel_launch(void* const* d_in, const int* in_sizes, int n_in,
                              void* d_out, int out_size)
{
    const float* x    = (const float*)d_in[0];
    const float* ln1g = (const float*)d_in[1];
    const float* ln1b = (const float*)d_in[2];
    const float* Wq   = (const float*)d_in[3];
    const float* Wk   = (const float*)d_in[4];
    const float* Wv   = (const float*)d_in[5];
    const float* Wo   = (const float*)d_in[6];
    const float* bo   = (const float*)d_in[7];
    const float* ln2g = (const float*)d_in[8];
    const float* ln2b = (const float*)d_in[9];
    const float* W1   = (const float*)d_in[10];
    const float* b1   = (const float*)d_in[11];
    const float* W2   = (const float*)d_in[12];
    const float* b2   = (const float*)d_in[13];
    float* out = (float*)d_out;

    float* x1;
    __half *ah, *al, *bh, *qh, *ql, *kh, *kl, *vh;
    __half *wqh, *wkh, *wvh, *woh, *w1h, *w2h;
    cudaGetSymbolAddress((void**)&x1,  g_x1);
    cudaGetSymbolAddress((void**)&ah,  g_ah);
    cudaGetSymbolAddress((void**)&al,  g_al);
    cudaGetSymbolAddress((void**)&bh,  g_bh);
    cudaGetSymbolAddress((void**)&qh,  g_qh);
    cudaGetSymbolAddress((void**)&ql,  g_ql);
    cudaGetSymbolAddress((void**)&kh,  g_kh);
    cudaGetSymbolAddress((void**)&kl,  g_kl);
    cudaGetSymbolAddress((void**)&vh,  g_vh);
    cudaGetSymbolAddress((void**)&wqh, g_wqh);
    cudaGetSymbolAddress((void**)&wkh, g_wkh);
    cudaGetSymbolAddress((void**)&wvh, g_wvh);
    cudaGetSymbolAddress((void**)&woh, g_woh);
    cudaGetSymbolAddress((void**)&w1h, g_w1h);
    cudaGetSymbolAddress((void**)&w2h, g_w2h);

    const int SM2 = 3 * 3 * G_TILE_B;   // 2-term: 3 stages x 48KB = 144KB
    const int SM1 = 3 * 2 * G_TILE_B;   // 1-term: 3 stages x 32KB = 96KB
    cudaFuncSetAttribute(gemm_mma<2>, cudaFuncAttributeMaxDynamicSharedMemorySize, SM2);
    cudaFuncSetAttribute(gemm_mma<1>, cudaFuncAttributeMaxDynamicSharedMemorySize, SM1);
    cudaFuncSetAttribute(attn_mma, cudaFuncAttributeMaxDynamicSharedMemorySize, AT_SMEM);

    dim3 tb(32, 8);
    wsplit_kernel<<<dim3(EDIM/32, EDIM/32), tb>>>(Wq, wqh, EDIM, EDIM);
    wsplit_kernel<<<dim3(EDIM/32, EDIM/32), tb>>>(Wk, wkh, EDIM, EDIM);
    wsplit_kernel<<<dim3(EDIM/32, EDIM/32), tb>>>(Wv, wvh, EDIM, EDIM);
    wsplit_kernel<<<dim3(EDIM/32, EDIM/32), tb>>>(Wo, woh, EDIM, EDIM);
    wsplit_kernel<<<dim3(FDIM/32, EDIM/32), tb>>>(W1, w1h, EDIM, FDIM);
    wsplit_kernel<<<dim3(EDIM/32, FDIM/32), tb>>>(W2, w2h, FDIM, EDIM);

    // 1. LN1 -> fp16 hi+lo
    ln_split_kernel<<<MTOK, 256>>>(x, ln1g, ln1b, ah, al);

    // 2. Q,K,V (2-term A)
    dim3 gE(EDIM/128, MTOK/128);
    gemm_mma<2><<<gE, 256, SM2>>>(ah, al, wqh, nullptr, qh, ql, nullptr, nullptr, 0, EDIM, EDIM);
    gemm_mma<2><<<gE, 256, SM2>>>(ah, al, wkh, nullptr, kh, kl, nullptr, nullptr, 0, EDIM, EDIM);
    gemm_mma<2><<<gE, 256, SM2>>>(ah, al, wvh, nullptr, vh, nullptr, nullptr, nullptr, 0, EDIM, EDIM);

    // 3. causal MHA -> fp16 hi
    attn_mma<<<dim3(TSEQ/128, NHEAD, BATCH), 256, AT_SMEM>>>(qh, ql, kh, kl, vh, ah);

    // 4. x1 = att @ Wo + bo + x  (1-term)
    gemm_mma<1><<<gE, 256, SM1>>>(ah, nullptr, woh, x1, nullptr, nullptr, bo, x, 0, EDIM, EDIM);

    // 5. LN2 -> fp16 hi only
    ln_split_kernel<<<MTOK, 256>>>(x1, ln2g, ln2b, ah, nullptr);

    // 6. hid = relu(h @ W1 + b1)  (1-term)
    dim3 gF(FDIM/128, MTOK/128);
    gemm_mma<1><<<gF, 256, SM1>>>(ah, nullptr, w1h, nullptr, bh, nullptr, b1, nullptr, 1, FDIM, EDIM);

    // 7. out = hid @ W2 + b2 + x1  (1-term)
    gemm_mma<1><<<gE, 256, SM1>>>(bh, nullptr, w2h, out, nullptr, nullptr, b2, x1, 0, EDIM, FDIM);
}

// round 7
// speedup vs baseline: 10.5085x; 1.0346x over previous
#include <cuda_runtime.h>
#include <cuda_fp16.h>
#include <cstdint>
#include <cstddef>

// Problem dims
#define BATCH 2
#define TSEQ  2048
#define EDIM  1024
#define FDIM  4096
#define NHEAD 16
#define HDIM  64
#define MTOK  (BATCH*TSEQ)   // 4096 rows
#define QKVN  (3*EDIM)       // 3072

// ---------------- scratch (device globals: allocation-free) ----------------
__device__ float  g_x1  [MTOK*EDIM];
__device__ __half g_ah  [MTOK*EDIM];     // ln outputs / attention output
__device__ __half g_al  [MTOK*EDIM];
__device__ __half g_bh  [MTOK*FDIM];     // mlp hidden
__device__ __half g_qkvh[MTOK*QKVN];     // fused QKV (hi)
__device__ __half g_ql  [MTOK*EDIM];     // Q lo plane
__device__ __half g_wqkv[QKVN*EDIM];     // [3072,1024] = Wq^T;Wk^T;Wv^T
__device__ __half g_woh [EDIM*EDIM];
__device__ __half g_w1h [FDIM*EDIM];
__device__ __half g_w2h [EDIM*FDIM];

// ---------------- PTX helpers (sm_80-compatible only) ----------------
__device__ __forceinline__ uint32_t smem_u32(const void* p) {
    uint32_t a;
    asm("{ .reg .u64 t; cvta.to.shared.u64 t, %1; cvt.u32.u64 %0, t; }" : "=r"(a) : "l"(p));
    return a;
}
#define SWZ128(o) ((o) ^ ((((uint32_t)(o)) >> 3) & 0x70u))

#define CP_ASYNC16(dst, src) \
    asm volatile("cp.async.cg.shared.global [%0], [%1], 16;" :: "r"(dst), "l"(src) : "memory")
#define CP_COMMIT()  asm volatile("cp.async.commit_group;" ::: "memory")
#define CP_WAIT(n)   asm volatile("cp.async.wait_group %0;" :: "n"(n) : "memory")

__device__ __forceinline__ void ldsm_x4(uint32_t* r, uint32_t addr) {
    asm volatile("ldmatrix.sync.aligned.m8n8.x4.shared.b16 {%0,%1,%2,%3}, [%4];"
                 : "=r"(r[0]), "=r"(r[1]), "=r"(r[2]), "=r"(r[3]) : "r"(addr));
}
__device__ __forceinline__ void ldsm_x2(uint32_t* r, uint32_t addr) {
    asm volatile("ldmatrix.sync.aligned.m8n8.x2.shared.b16 {%0,%1}, [%2];"
                 : "=r"(r[0]), "=r"(r[1]) : "r"(addr));
}
__device__ __forceinline__ void ldsm_x2t(uint32_t* r, uint32_t addr) {
    asm volatile("ldmatrix.sync.aligned.m8n8.x2.trans.shared.b16 {%0,%1}, [%2];"
                 : "=r"(r[0]), "=r"(r[1]) : "r"(addr));
}
__device__ __forceinline__ void mma16816(float* c, const uint32_t* a, const uint32_t* b) {
    asm volatile("mma.sync.aligned.m16n8k16.row.col.f32.f16.f16.f32 "
                 "{%0,%1,%2,%3}, {%4,%5,%6,%7}, {%8,%9}, {%0,%1,%2,%3};"
                 : "+f"(c[0]), "+f"(c[1]), "+f"(c[2]), "+f"(c[3])
                 : "r"(a[0]), "r"(a[1]), "r"(a[2]), "r"(a[3]),
                   "r"(b[0]), "r"(b[1]));
}
__device__ __forceinline__ uint32_t packh2(float a, float b) {
    __half2 t = __floats2half2_rn(a, b);
    return *(uint32_t*)&t;
}

// ---------------- fused LayerNorm -> fp16 (optional lo split) ----------------
__global__ __launch_bounds__(256)
void ln_split_kernel(const float* __restrict__ x, const float* __restrict__ g,
                     const float* __restrict__ b, __half* __restrict__ yh,
                     __half* __restrict__ yl)
{
    __shared__ float red[8];
    int row = blockIdx.x;
    int t = threadIdx.x;
    const float4* xr = (const float4*)(x + (size_t)row * EDIM);
    float4 v = xr[t];
    float s = v.x + v.y + v.z + v.w;
    #pragma unroll
    for (int o = 16; o > 0; o >>= 1) s += __shfl_xor_sync(0xffffffffu, s, o);
    if ((t & 31) == 0) red[t >> 5] = s;
    __syncthreads();
    float tot = 0.f;
    #pragma unroll
    for (int i = 0; i < 8; i++) tot += red[i];
    float mean = tot * (1.0f / EDIM);
    float dx = v.x - mean, dy = v.y - mean, dz = v.z - mean, dw = v.w - mean;
    float s2 = dx*dx + dy*dy + dz*dz + dw*dw;
    __syncthreads();
    #pragma unroll
    for (int o = 16; o > 0; o >>= 1) s2 += __shfl_xor_sync(0xffffffffu, s2, o);
    if ((t & 31) == 0) red[t >> 5] = s2;
    __syncthreads();
    float tot2 = 0.f;
    #pragma unroll
    for (int i = 0; i < 8; i++) tot2 += red[i];
    float r = rsqrtf(tot2 * (1.0f / EDIM) + 1e-5f);
    float4 g4 = ((const float4*)g)[t];
    float4 b4 = ((const float4*)b)[t];
    float o0 = dx * r * g4.x + b4.x;
    float o1 = dy * r * g4.y + b4.y;
    float o2 = dz * r * g4.z + b4.z;
    float o3 = dw * r * g4.w + b4.w;
    __half h0 = __float2half_rn(o0), h1 = __float2half_rn(o1);
    __half h2 = __float2half_rn(o2), h3 = __float2half_rn(o3);
    size_t base = (size_t)row * EDIM + t * 4;
    *(__half2*)(yh + base)     = __half2(h0, h1);
    *(__half2*)(yh + base + 2) = __half2(h2, h3);
    if (yl) {
        *(__half2*)(yl + base) =
            __half2(__float2half_rn(o0 - __half2float(h0)),
                    __float2half_rn(o1 - __half2float(h1)));
        *(__half2*)(yl + base + 2) =
            __half2(__float2half_rn(o2 - __half2float(h2)),
                    __float2half_rn(o3 - __half2float(h3)));
    }
}

// ---------------- weight transpose W[K,N] -> T[N,K] fp16, 64x64 tiles --------
__global__ __launch_bounds__(256)
void wtrans_kernel(const float* __restrict__ W, __half* __restrict__ T,
                   int K, int N)
{
    __shared__ float tile[64][65];
    int bx = blockIdx.x * 64;   // N
    int by = blockIdx.y * 64;   // K
    int tid = threadIdx.x;
    int lr = tid >> 4;              // 0..15
    int lc = (tid & 15) * 4;        // float4 col
    #pragma unroll
    for (int j = 0; j < 64; j += 16) {
        float4 v = *(const float4*)(W + (size_t)(by + lr + j) * N + bx + lc);
        tile[lr + j][lc]     = v.x;
        tile[lr + j][lc + 1] = v.y;
        tile[lr + j][lc + 2] = v.z;
        tile[lr + j][lc + 3] = v.w;
    }
    __syncthreads();
    int sr = tid >> 5;              // 0..7 (n row)
    int sc = (tid & 31) * 2;        // k pair
    #pragma unroll
    for (int j = 0; j < 64; j += 8) {
        int n = sr + j;
        __half2 h = __floats2half2_rn(tile[sc][n], tile[sc + 1][n]);
        *(__half2*)(T + (size_t)(bx + n) * K + by + sc) = h;
    }
}

// ---------------- mma.sync fp16 GEMM (TERMS = 1 or 2 A-planes) ---------------
// C[M,N] = (Ah[+Al])[M,K] @ Bh[N,K]^T. Tile 128x128, K-chunk 64, 8 warps 2x4,
// 3-stage cp.async pipeline. Optional fp16 hi (+lo for col<lo_limit) output.
#define G_TILE_B 16384

template<int TERMS>
__global__ __launch_bounds__(256, 1)
void gemm_mma(const __half* __restrict__ Ah, const __half* __restrict__ Al,
              const __half* __restrict__ Bh,
              float* __restrict__ C, __half* __restrict__ Oh,
              __half* __restrict__ Ol, int lo_limit, int lo_ld,
              const float* __restrict__ bias,
              const float* __restrict__ resid, int relu, int N, int K)
{
    const int NT = TERMS + 1;
    const uint32_t STAGE_B = NT * G_TILE_B;
    extern __shared__ __align__(1024) char smem[];
    const uint32_t sb = smem_u32(smem);
    const int tid  = threadIdx.x;
    const int wid  = tid >> 5, lane = tid & 31;
    const int wm   = wid >> 2;
    const int wn   = wid & 3;
    const int bm = blockIdx.y, bn = blockIdx.x;

    const size_t arow0 = (size_t)bm * 128;
    const size_t brow0 = (size_t)bn * 128;

    auto load_stage = [&](int s, int k0) {
        uint32_t base = sb + s * STAGE_B;
        #pragma unroll
        for (int it = 0; it < 4 * NT; it++) {
            int c   = tid + it * 256;
            int tl  = c >> 10;
            int idx = c & 1023;
            int r   = idx >> 3;
            int c16 = idx & 7;
            uint32_t dst = base + tl * G_TILE_B + SWZ128(r * 128 + c16 * 16);
            const __half* src;
            if (tl == 0)                       src = Ah + (arow0 + r) * K + k0 + c16 * 8;
            else if (TERMS == 2 && tl == 1)    src = Al + (arow0 + r) * K + k0 + c16 * 8;
            else                               src = Bh + (brow0 + r) * K + k0 + c16 * 8;
            CP_ASYNC16(dst, src);
        }
        CP_COMMIT();
    };

    float acc[4][4][4];
    #pragma unroll
    for (int mf = 0; mf < 4; mf++)
        #pragma unroll
        for (int nf = 0; nf < 4; nf++)
            #pragma unroll
            for (int e = 0; e < 4; e++) acc[mf][nf][e] = 0.f;

    const int nch = K >> 6;
    load_stage(0, 0);
    load_stage(1, 64);

    const int a_r  = (lane & 7) + ((lane >> 3) & 1) * 8;
    const int a_cb = (lane >> 4) * 16;
    const int b_l  = lane & 15;
    const int b_r  = b_l & 7;
    const int b_cb = ((b_l >> 3) & 1) * 16;

    int s3 = 0;
    for (int i = 0; i < nch; i++) {
        if (i + 2 < nch) {
            int sn = s3 + 2; if (sn >= 3) sn -= 3;
            load_stage(sn, (i + 2) << 6);
            CP_WAIT(2);
        } else if (i + 1 < nch) {
            CP_WAIT(1);
        } else {
            CP_WAIT(0);
        }
        __syncthreads();

        uint32_t tAh = sb + s3 * STAGE_B;
        uint32_t tAl = tAh + G_TILE_B;
        uint32_t tBh = tAh + (NT - 1) * G_TILE_B;

        #pragma unroll
        for (int ks = 0; ks < 4; ks++) {
            uint32_t rah[4][4], ral[4][4], rbh[4][2];
            #pragma unroll
            for (int mf = 0; mf < 4; mf++) {
                uint32_t off = SWZ128((wm * 64 + mf * 16 + a_r) * 128 + ks * 32 + a_cb);
                ldsm_x4(rah[mf], tAh + off);
                if (TERMS == 2) ldsm_x4(ral[mf], tAl + off);
            }
            #pragma unroll
            for (int nf = 0; nf < 4; nf++) {
                uint32_t off = SWZ128((wn * 32 + nf * 8 + b_r) * 128 + ks * 32 + b_cb);
                ldsm_x2(rbh[nf], tBh + off);
            }
            #pragma unroll
            for (int mf = 0; mf < 4; mf++)
                #pragma unroll
                for (int nf = 0; nf < 4; nf++) {
                    mma16816(acc[mf][nf], rah[mf], rbh[nf]);
                    if (TERMS == 2) mma16816(acc[mf][nf], ral[mf], rbh[nf]);
                }
        }
        __syncthreads();
        if (++s3 == 3) s3 = 0;
    }

    int rbase = bm * 128 + wm * 64 + (lane >> 2);
    int cbase = bn * 128 + wn * 32 + (lane & 3) * 2;
    #pragma unroll
    for (int mf = 0; mf < 4; mf++) {
        #pragma unroll
        for (int half = 0; half < 2; half++) {
            int row = rbase + mf * 16 + half * 8;
            #pragma unroll
            for (int nf = 0; nf < 4; nf++) {
                int col = cbase + nf * 8;
                float ox = acc[mf][nf][half * 2 + 0];
                float oy = acc[mf][nf][half * 2 + 1];
                if (bias) {
                    float2 bb = *(const float2*)(bias + col);
                    ox += bb.x; oy += bb.y;
                }
                if (relu) { ox = fmaxf(ox, 0.f); oy = fmaxf(oy, 0.f); }
                if (resid) {
                    float2 rr = *(const float2*)(resid + (size_t)row * N + col);
                    ox += rr.x; oy += rr.y;
                }
                if (C) {
                    float2 o2; o2.x = ox; o2.y = oy;
                    *(float2*)(C + (size_t)row * N + col) = o2;
                }
                if (Oh) {
                    __half hx = __float2half_rn(ox);
                    __half hy = __float2half_rn(oy);
                    *(__half2*)(Oh + (size_t)row * N + col) = __half2(hx, hy);
                    if (Ol && col < lo_limit)
                        *(__half2*)(Ol + (size_t)row * lo_ld + col) =
                            __half2(__float2half_rn(ox - __half2float(hx)),
                                    __float2half_rn(oy - __half2float(hy)));
                }
            }
        }
    }
}

// ---------------- tensor-core causal flash attention --------------------------
// 128 queries/block, 8 warps, 64-key tiles double-buffered.
// QK^T: 2-term (Q hi/lo, K hi). PV: 2-term (P hi/lo, V hi).
// QKV packed [row][3072]: Q@0, K@1024, V@2048. Q-lo separate [row][1024].
#define AT_STAGE 16384
#define AT_SMEM  (32768 + 2*AT_STAGE)

__global__ __launch_bounds__(256, 1)
void attn_mma(const __half* __restrict__ QKV, const __half* __restrict__ Ql,
              __half* __restrict__ Oh)
{
    extern __shared__ __align__(1024) char smem[];
    const uint32_t sb = smem_u32(smem);
    const int tid = threadIdx.x, wid = tid >> 5, lane = tid & 31;
    const int qt = blockIdx.x, h = blockIdx.y, b = blockIdx.z;
    const int q0 = qt * 128;
    const size_t hoff = (size_t)h * HDIM;

    // Q hi + lo: 2 x 128 rows x 8 chunks
    #pragma unroll
    for (int it = 0; it < 8; it++) {
        int idx = tid + it * 256;
        int tl = idx >> 10, r = (idx >> 3) & 127, c16 = idx & 7;
        uint32_t dst = sb + tl * 16384 + SWZ128(r * 128 + c16 * 16);
        const __half* src = tl
            ? Ql  + (size_t)(b * TSEQ + q0 + r) * EDIM + hoff + c16 * 8
            : QKV + (size_t)(b * TSEQ + q0 + r) * QKVN + hoff + c16 * 8;
        CP_ASYNC16(dst, src);
    }
    auto load_kv = [&](int s, int kbase) {
        uint32_t base = sb + 32768 + s * AT_STAGE;
        #pragma unroll
        for (int it = 0; it < 4; it++) {
            int idx = tid + it * 256;
            int tl = idx >> 9, r = (idx >> 3) & 63, c16 = idx & 7;
            uint32_t dst = base + tl * 8192 + SWZ128(r * 128 + c16 * 16);
            const __half* src = QKV + (size_t)(b * TSEQ + kbase + r) * QKVN
                                + (tl ? 2048 : 1024) + hoff + c16 * 8;
            CP_ASYNC16(dst, src);
        }
        CP_COMMIT();
    };
    load_kv(0, 0);

    const int a_r  = (lane & 7) + ((lane >> 3) & 1) * 8;
    const int a_cb = (lane >> 4) * 16;
    const int b_l  = lane & 15;
    const int b_r  = b_l & 7;
    const int b_cb = ((b_l >> 3) & 1) * 16;
    const int rA   = q0 + wid * 16 + (lane >> 2);
    const int wrowmax = q0 + wid * 16 + 15;

    float mrow[2] = {-1e30f, -1e30f};
    float lrow[2] = {0.f, 0.f};
    float o[8][4];
    #pragma unroll
    for (int nf = 0; nf < 8; nf++)
        #pragma unroll
        for (int e = 0; e < 4; e++) o[nf][e] = 0.f;
    uint32_t rah[4][4], ral[4][4];

    const int nkt = (q0 + 128) / 64;
    for (int kt = 0; kt < nkt; kt++) {
        if (kt + 1 < nkt) { load_kv((kt + 1) & 1, (kt + 1) * 64); CP_WAIT(1); }
        else              { CP_WAIT(0); }
        __syncthreads();
        if (kt == 0) {
            #pragma unroll
            for (int ks = 0; ks < 4; ks++) {
                uint32_t off = SWZ128((wid * 16 + a_r) * 128 + ks * 32 + a_cb);
                ldsm_x4(rah[ks], sb + off);
                ldsm_x4(ral[ks], sb + 16384 + off);
            }
        }
        if (kt * 64 <= wrowmax) {
            uint32_t kb = sb + 32768 + (kt & 1) * AT_STAGE;
            float s[8][4];
            #pragma unroll
            for (int nf = 0; nf < 8; nf++)
                #pragma unroll
                for (int e = 0; e < 4; e++) s[nf][e] = 0.f;

            #pragma unroll
            for (int ks = 0; ks < 4; ks++) {
                #pragma unroll
                for (int nf = 0; nf < 8; nf++) {
                    uint32_t koff = SWZ128((nf * 8 + b_r) * 128 + ks * 32 + b_cb);
                    uint32_t kbh[2];
                    ldsm_x2(kbh, kb + koff);
                    mma16816(s[nf], rah[ks], kbh);
                    mma16816(s[nf], ral[ks], kbh);
                }
            }
            #pragma unroll
            for (int nf = 0; nf < 8; nf++) {
                int col = kt * 64 + nf * 8 + (lane & 3) * 2;
                s[nf][0] = (col     > rA)     ? -1e30f : s[nf][0] * 0.125f;
                s[nf][1] = (col + 1 > rA)     ? -1e30f : s[nf][1] * 0.125f;
                s[nf][2] = (col     > rA + 8) ? -1e30f : s[nf][2] * 0.125f;
                s[nf][3] = (col + 1 > rA + 8) ? -1e30f : s[nf][3] * 0.125f;
            }
            float tmA = -1e30f, tmB = -1e30f;
            #pragma unroll
            for (int nf = 0; nf < 8; nf++) {
                tmA = fmaxf(tmA, fmaxf(s[nf][0], s[nf][1]));
                tmB = fmaxf(tmB, fmaxf(s[nf][2], s[nf][3]));
            }
            tmA = fmaxf(tmA, __shfl_xor_sync(0xffffffffu, tmA, 1));
            tmA = fmaxf(tmA, __shfl_xor_sync(0xffffffffu, tmA, 2));
            tmB = fmaxf(tmB, __shfl_xor_sync(0xffffffffu, tmB, 1));
            tmB = fmaxf(tmB, __shfl_xor_sync(0xffffffffu, tmB, 2));
            float mnA = fmaxf(mrow[0], tmA), mnB = fmaxf(mrow[1], tmB);
            float cA = __expf(mrow[0] - mnA), cB = __expf(mrow[1] - mnB);
            float lsA = 0.f, lsB = 0.f;
            #pragma unroll
            for (int nf = 0; nf < 8; nf++) {
                s[nf][0] = __expf(s[nf][0] - mnA);
                s[nf][1] = __expf(s[nf][1] - mnA);
                s[nf][2] = __expf(s[nf][2] - mnB);
                s[nf][3] = __expf(s[nf][3] - mnB);
                lsA += s[nf][0] + s[nf][1];
                lsB += s[nf][2] + s[nf][3];
            }
            lsA += __shfl_xor_sync(0xffffffffu, lsA, 1);
            lsA += __shfl_xor_sync(0xffffffffu, lsA, 2);
            lsB += __shfl_xor_sync(0xffffffffu, lsB, 1);
            lsB += __shfl_xor_sync(0xffffffffu, lsB, 2);
            lrow[0] = lrow[0] * cA + lsA; mrow[0] = mnA;
            lrow[1] = lrow[1] * cB + lsB; mrow[1] = mnB;
            #pragma unroll
            for (int nf = 0; nf < 8; nf++) {
                o[nf][0] *= cA; o[nf][1] *= cA;
                o[nf][2] *= cB; o[nf][3] *= cB;
            }
            #pragma unroll
            for (int ks = 0; ks < 4; ks++) {
                uint32_t phi[4], plo[4];
                {
                    float* f0 = s[2 * ks];
                    float* f1 = s[2 * ks + 1];
                    phi[0] = packh2(f0[0], f0[1]);
                    phi[1] = packh2(f0[2], f0[3]);
                    phi[2] = packh2(f1[0], f1[1]);
                    phi[3] = packh2(f1[2], f1[3]);
                    __half2* hp;
                    hp = (__half2*)&phi[0];
                    plo[0] = packh2(f0[0] - __half2float(hp->x), f0[1] - __half2float(hp->y));
                    hp = (__half2*)&phi[1];
                    plo[1] = packh2(f0[2] - __half2float(hp->x), f0[3] - __half2float(hp->y));
                    hp = (__half2*)&phi[2];
                    plo[2] = packh2(f1[0] - __half2float(hp->x), f1[1] - __half2float(hp->y));
                    hp = (__half2*)&phi[3];
                    plo[3] = packh2(f1[2] - __half2float(hp->x), f1[3] - __half2float(hp->y));
                }
                #pragma unroll
                for (int nf = 0; nf < 8; nf++) {
                    uint32_t voff = SWZ128((ks * 16 + b_l) * 128 + nf * 16);
                    uint32_t vbh[2];
                    ldsm_x2t(vbh, kb + 8192 + voff);
                    mma16816(o[nf], phi, vbh);
                    mma16816(o[nf], plo, vbh);
                }
            }
        }
        __syncthreads();
    }

    float iA = 1.f / lrow[0], iB = 1.f / lrow[1];
    #pragma unroll
    for (int nf = 0; nf < 8; nf++) {
        int col = nf * 8 + (lane & 3) * 2;
        float v0 = o[nf][0] * iA, v1 = o[nf][1] * iA;
        float v2 = o[nf][2] * iB, v3 = o[nf][3] * iB;
        size_t baseA = (size_t)(b * TSEQ + rA) * EDIM + hoff + col;
        size_t baseB = (size_t)(b * TSEQ + rA + 8) * EDIM + hoff + col;
        *(__half2*)(Oh + baseA) = __floats2half2_rn(v0, v1);
        *(__half2*)(Oh + baseB) = __floats2half2_rn(v2, v3);
    }
}

// ---------------- launch -----------------------------------------------------
extern "C" void kernel_launch(void* const* d_in, const int* in_sizes, int n_in,
                              void* d_out, int out_size)
{
    const float* x    = (const float*)d_in[0];
    const float* ln1g = (const float*)d_in[1];
    const float* ln1b = (const float*)d_in[2];
    const float* Wq   = (const float*)d_in[3];
    const float* Wk   = (const float*)d_in[4];
    const float* Wv   = (const float*)d_in[5];
    const float* Wo   = (const float*)d_in[6];
    const float* bo   = (const float*)d_in[7];
    const float* ln2g = (const float*)d_in[8];
    const float* ln2b = (const float*)d_in[9];
    const float* W1   = (const float*)d_in[10];
    const float* b1   = (const float*)d_in[11];
    const float* W2   = (const float*)d_in[12];
    const float* b2   = (const float*)d_in[13];
    float* out = (float*)d_out;

    float* x1;
    __half *ah, *al, *bh, *qkvh, *ql;
    __half *wqkv, *woh, *w1h, *w2h;
    cudaGetSymbolAddress((void**)&x1,   g_x1);
    cudaGetSymbolAddress((void**)&ah,   g_ah);
    cudaGetSymbolAddress((void**)&al,   g_al);
    cudaGetSymbolAddress((void**)&bh,   g_bh);
    cudaGetSymbolAddress((void**)&qkvh, g_qkvh);
    cudaGetSymbolAddress((void**)&ql,   g_ql);
    cudaGetSymbolAddress((void**)&wqkv, g_wqkv);
    cudaGetSymbolAddress((void**)&woh,  g_woh);
    cudaGetSymbolAddress((void**)&w1h,  g_w1h);
    cudaGetSymbolAddress((void**)&w2h,  g_w2h);

    const int SM2 = 3 * 3 * G_TILE_B;   // 144KB
    const int SM1 = 3 * 2 * G_TILE_B;   // 96KB
    cudaFuncSetAttribute(gemm_mma<2>, cudaFuncAttributeMaxDynamicSharedMemorySize, SM2);
    cudaFuncSetAttribute(gemm_mma<1>, cudaFuncAttributeMaxDynamicSharedMemorySize, SM1);
    cudaFuncSetAttribute(attn_mma, cudaFuncAttributeMaxDynamicSharedMemorySize, AT_SMEM);

    // weight transposes (fp16): Wq/Wk/Wv concatenated into wqkv [3072,1024]
    wtrans_kernel<<<dim3(EDIM/64, EDIM/64), 256>>>(Wq, wqkv,                EDIM, EDIM);
    wtrans_kernel<<<dim3(EDIM/64, EDIM/64), 256>>>(Wk, wqkv + EDIM*EDIM,    EDIM, EDIM);
    wtrans_kernel<<<dim3(EDIM/64, EDIM/64), 256>>>(Wv, wqkv + 2*EDIM*EDIM,  EDIM, EDIM);
    wtrans_kernel<<<dim3(EDIM/64, EDIM/64), 256>>>(Wo, woh,  EDIM, EDIM);
    wtrans_kernel<<<dim3(FDIM/64, EDIM/64), 256>>>(W1, w1h,  EDIM, FDIM);
    wtrans_kernel<<<dim3(EDIM/64, FDIM/64), 256>>>(W2, w2h,  FDIM, EDIM);

    // 1. LN1 -> fp16 hi+lo
    ln_split_kernel<<<MTOK, 256>>>(x, ln1g, ln1b, ah, al);

    // 2. fused QKV (2-term A): N=3072; lo plane only for Q columns
    dim3 gQKV(QKVN/128, MTOK/128);
    gemm_mma<2><<<gQKV, 256, SM2>>>(ah, al, wqkv, nullptr, qkvh, ql, EDIM, EDIM,
                                    nullptr, nullptr, 0, QKVN, EDIM);

    // 3. causal MHA -> fp16 hi
    attn_mma<<<dim3(TSEQ/128, NHEAD, BATCH), 256, AT_SMEM>>>(qkvh, ql, ah);

    // 4. x1 = att @ Wo + bo + x  (1-term)
    dim3 gE(EDIM/128, MTOK/128);
    gemm_mma<1><<<gE, 256, SM1>>>(ah, nullptr, woh, x1, nullptr, nullptr, 0, 0,
                                  bo, x, 0, EDIM, EDIM);

    // 5. LN2 -> fp16 hi only
    ln_split_kernel<<<MTOK, 256>>>(x1, ln2g, ln2b, ah, nullptr);

    // 6. hid = relu(h @ W1 + b1)  (1-term)
    dim3 gF(FDIM/128, MTOK/128);
    gemm_mma<1><<<gF, 256, SM1>>>(ah, nullptr, w1h, nullptr, bh, nullptr, 0, 0,
                                  b1, nullptr, 1, FDIM, EDIM);

    // 7. out = hid @ W2 + b2 + x1  (1-term)
    gemm_mma<1><<<gE, 256, SM1>>>(bh, nullptr, w2h, out, nullptr, nullptr, 0, 0,
                                  b2, x1, 0, EDIM, FDIM);
}

// round 8
// speedup vs baseline: 12.9606x; 1.2333x over previous
#include <cuda_runtime.h>
#include <cuda_fp16.h>
#include <cstdint>
#include <cstddef>

// Problem dims
#define BATCH 2
#define TSEQ  2048
#define EDIM  1024
#define FDIM  4096
#define NHEAD 16
#define HDIM  64
#define MTOK  (BATCH*TSEQ)   // 4096 rows
#define QKVN  (3*EDIM)       // 3072

// ---------------- scratch (device globals: allocation-free) ----------------
__device__ float  g_x1  [MTOK*EDIM];
__device__ __half g_ah  [MTOK*EDIM];     // ln outputs / attention output
__device__ __half g_bh  [MTOK*FDIM];     // mlp hidden
__device__ __half g_qkvh[MTOK*QKVN];     // fused QKV
__device__ __half g_wqkv[QKVN*EDIM];     // [3072,1024] = Wq^T;Wk^T;Wv^T
__device__ __half g_woh [EDIM*EDIM];
__device__ __half g_w1h [FDIM*EDIM];
__device__ __half g_w2h [EDIM*FDIM];

// ---------------- PTX helpers (sm_80-compatible only) ----------------
__device__ __forceinline__ uint32_t smem_u32(const void* p) {
    uint32_t a;
    asm("{ .reg .u64 t; cvta.to.shared.u64 t, %1; cvt.u32.u64 %0, t; }" : "=r"(a) : "l"(p));
    return a;
}
#define SWZ128(o) ((o) ^ ((((uint32_t)(o)) >> 3) & 0x70u))

#define CP_ASYNC16(dst, src) \
    asm volatile("cp.async.cg.shared.global [%0], [%1], 16;" :: "r"(dst), "l"(src) : "memory")
#define CP_COMMIT()  asm volatile("cp.async.commit_group;" ::: "memory")
#define CP_WAIT(n)   asm volatile("cp.async.wait_group %0;" :: "n"(n) : "memory")

__device__ __forceinline__ void ldsm_x4(uint32_t* r, uint32_t addr) {
    asm volatile("ldmatrix.sync.aligned.m8n8.x4.shared.b16 {%0,%1,%2,%3}, [%4];"
                 : "=r"(r[0]), "=r"(r[1]), "=r"(r[2]), "=r"(r[3]) : "r"(addr));
}
__device__ __forceinline__ void ldsm_x2(uint32_t* r, uint32_t addr) {
    asm volatile("ldmatrix.sync.aligned.m8n8.x2.shared.b16 {%0,%1}, [%2];"
                 : "=r"(r[0]), "=r"(r[1]) : "r"(addr));
}
__device__ __forceinline__ void ldsm_x2t(uint32_t* r, uint32_t addr) {
    asm volatile("ldmatrix.sync.aligned.m8n8.x2.trans.shared.b16 {%0,%1}, [%2];"
                 : "=r"(r[0]), "=r"(r[1]) : "r"(addr));
}
__device__ __forceinline__ void mma16816(float* c, const uint32_t* a, const uint32_t* b) {
    asm volatile("mma.sync.aligned.m16n8k16.row.col.f32.f16.f16.f32 "
                 "{%0,%1,%2,%3}, {%4,%5,%6,%7}, {%8,%9}, {%0,%1,%2,%3};"
                 : "+f"(c[0]), "+f"(c[1]), "+f"(c[2]), "+f"(c[3])
                 : "r"(a[0]), "r"(a[1]), "r"(a[2]), "r"(a[3]),
                   "r"(b[0]), "r"(b[1]));
}
__device__ __forceinline__ uint32_t packh2(float a, float b) {
    __half2 t = __floats2half2_rn(a, b);
    return *(uint32_t*)&t;
}

// ---------------- fused LayerNorm -> fp16 ----------------
__global__ __launch_bounds__(256)
void ln_kernel(const float* __restrict__ x, const float* __restrict__ g,
               const float* __restrict__ b, __half* __restrict__ yh)
{
    __shared__ float red[8];
    int row = blockIdx.x;
    int t = threadIdx.x;
    const float4* xr = (const float4*)(x + (size_t)row * EDIM);
    float4 v = xr[t];
    float s = v.x + v.y + v.z + v.w;
    #pragma unroll
    for (int o = 16; o > 0; o >>= 1) s += __shfl_xor_sync(0xffffffffu, s, o);
    if ((t & 31) == 0) red[t >> 5] = s;
    __syncthreads();
    float tot = 0.f;
    #pragma unroll
    for (int i = 0; i < 8; i++) tot += red[i];
    float mean = tot * (1.0f / EDIM);
    float dx = v.x - mean, dy = v.y - mean, dz = v.z - mean, dw = v.w - mean;
    float s2 = dx*dx + dy*dy + dz*dz + dw*dw;
    __syncthreads();
    #pragma unroll
    for (int o = 16; o > 0; o >>= 1) s2 += __shfl_xor_sync(0xffffffffu, s2, o);
    if ((t & 31) == 0) red[t >> 5] = s2;
    __syncthreads();
    float tot2 = 0.f;
    #pragma unroll
    for (int i = 0; i < 8; i++) tot2 += red[i];
    float r = rsqrtf(tot2 * (1.0f / EDIM) + 1e-5f);
    float4 g4 = ((const float4*)g)[t];
    float4 b4 = ((const float4*)b)[t];
    float o0 = dx * r * g4.x + b4.x;
    float o1 = dy * r * g4.y + b4.y;
    float o2 = dz * r * g4.z + b4.z;
    float o3 = dw * r * g4.w + b4.w;
    size_t base = (size_t)row * EDIM + t * 4;
    *(__half2*)(g_ah + base - ((size_t)row * EDIM + t * 4) + base) = __floats2half2_rn(o0, o1); // placeholder avoided below
    *(__half2*)(yh + base)     = __floats2half2_rn(o0, o1);
    *(__half2*)(yh + base + 2) = __floats2half2_rn(o2, o3);
}

// ---------------- batched weight transpose: all 6 weights, one launch --------
// W[K,N] fp32 -> T[N,K] fp16, 64x64 tiles.
__global__ __launch_bounds__(256)
void wtrans_all(const float* __restrict__ Wq, const float* __restrict__ Wk,
                const float* __restrict__ Wv, const float* __restrict__ Wo,
                const float* __restrict__ W1, const float* __restrict__ W2,
                __half* __restrict__ wqkv, __half* __restrict__ woh,
                __half* __restrict__ w1h, __half* __restrict__ w2h)
{
    __shared__ float tile[64][65];
    int bid = blockIdx.x;
    const float* W; __half* T; int K, N, bx, by;
    if (bid < 1024) {
        int seg = bid >> 8, loc = bid & 255;
        W = (seg == 0) ? Wq : (seg == 1) ? Wk : (seg == 2) ? Wv : Wo;
        T = (seg == 0) ? wqkv : (seg == 1) ? wqkv + EDIM*EDIM
          : (seg == 2) ? wqkv + 2*EDIM*EDIM : woh;
        K = EDIM; N = EDIM;
        bx = (loc & 15) * 64; by = (loc >> 4) * 64;
    } else if (bid < 2048) {
        int loc = bid - 1024;
        W = W1; T = w1h; K = EDIM; N = FDIM;
        bx = (loc & 63) * 64; by = (loc >> 6) * 64;
    } else {
        int loc = bid - 2048;
        W = W2; T = w2h; K = FDIM; N = EDIM;
        bx = (loc & 15) * 64; by = (loc >> 4) * 64;
    }
    int tid = threadIdx.x;
    int lr = tid >> 4;
    int lc = (tid & 15) * 4;
    #pragma unroll
    for (int j = 0; j < 64; j += 16) {
        float4 v = *(const float4*)(W + (size_t)(by + lr + j) * N + bx + lc);
        tile[lr + j][lc]     = v.x;
        tile[lr + j][lc + 1] = v.y;
        tile[lr + j][lc + 2] = v.z;
        tile[lr + j][lc + 3] = v.w;
    }
    __syncthreads();
    int sr = tid >> 5;
    int sc = (tid & 31) * 2;
    #pragma unroll
    for (int j = 0; j < 64; j += 8) {
        int n = sr + j;
        __half2 h = __floats2half2_rn(tile[sc][n], tile[sc + 1][n]);
        *(__half2*)(T + (size_t)(bx + n) * K + by + sc) = h;
    }
}

// ---------------- mma.sync fp16 GEMM (1-term) --------------------------------
// C[M,N] = A[M,K] @ B[N,K]^T. Tile 128x128, K-chunk 64, 8 warps 2x4,
// 3-stage cp.async pipeline. Output: fp32 C and/or fp16 Oh, fused epilogue.
#define G_TILE_B 16384
#define G_STAGE_B (2*G_TILE_B)
#define G_SMEM (3*G_STAGE_B)     // 96 KB

__global__ __launch_bounds__(256, 1)
void gemm_mma(const __half* __restrict__ Ah, const __half* __restrict__ Bh,
              float* __restrict__ C, __half* __restrict__ Oh,
              const float* __restrict__ bias,
              const float* __restrict__ resid, int relu, int N, int K)
{
    extern __shared__ __align__(1024) char smem[];
    const uint32_t sb = smem_u32(smem);
    const int tid  = threadIdx.x;
    const int wid  = tid >> 5, lane = tid & 31;
    const int wm   = wid >> 2;
    const int wn   = wid & 3;
    const int bm = blockIdx.y, bn = blockIdx.x;

    const size_t arow0 = (size_t)bm * 128;
    const size_t brow0 = (size_t)bn * 128;

    auto load_stage = [&](int s, int k0) {
        uint32_t base = sb + s * G_STAGE_B;
        #pragma unroll
        for (int it = 0; it < 8; it++) {
            int c   = tid + it * 256;
            int tl  = c >> 10;
            int idx = c & 1023;
            int r   = idx >> 3;
            int c16 = idx & 7;
            uint32_t dst = base + tl * G_TILE_B + SWZ128(r * 128 + c16 * 16);
            const __half* src = tl
                ? Bh + (brow0 + r) * K + k0 + c16 * 8
                : Ah + (arow0 + r) * K + k0 + c16 * 8;
            CP_ASYNC16(dst, src);
        }
        CP_COMMIT();
    };

    float acc[4][4][4];
    #pragma unroll
    for (int mf = 0; mf < 4; mf++)
        #pragma unroll
        for (int nf = 0; nf < 4; nf++)
            #pragma unroll
            for (int e = 0; e < 4; e++) acc[mf][nf][e] = 0.f;

    const int nch = K >> 6;
    load_stage(0, 0);
    load_stage(1, 64);

    const int a_r  = (lane & 7) + ((lane >> 3) & 1) * 8;
    const int a_cb = (lane >> 4) * 16;
    const int b_l  = lane & 15;
    const int b_r  = b_l & 7;
    const int b_cb = ((b_l >> 3) & 1) * 16;

    int s3 = 0;
    for (int i = 0; i < nch; i++) {
        if (i + 2 < nch) {
            int sn = s3 + 2; if (sn >= 3) sn -= 3;
            load_stage(sn, (i + 2) << 6);
            CP_WAIT(2);
        } else if (i + 1 < nch) {
            CP_WAIT(1);
        } else {
            CP_WAIT(0);
        }
        __syncthreads();

        uint32_t tA = sb + s3 * G_STAGE_B;
        uint32_t tB = tA + G_TILE_B;

        #pragma unroll
        for (int ks = 0; ks < 4; ks++) {
            uint32_t ra[4][4], rb[4][2];
            #pragma unroll
            for (int mf = 0; mf < 4; mf++) {
                uint32_t off = SWZ128((wm * 64 + mf * 16 + a_r) * 128 + ks * 32 + a_cb);
                ldsm_x4(ra[mf], tA + off);
            }
            #pragma unroll
            for (int nf = 0; nf < 4; nf++) {
                uint32_t off = SWZ128((wn * 32 + nf * 8 + b_r) * 128 + ks * 32 + b_cb);
                ldsm_x2(rb[nf], tB + off);
            }
            #pragma unroll
            for (int mf = 0; mf < 4; mf++)
                #pragma unroll
                for (int nf = 0; nf < 4; nf++)
                    mma16816(acc[mf][nf], ra[mf], rb[nf]);
        }
        __syncthreads();
        if (++s3 == 3) s3 = 0;
    }

    int rbase = bm * 128 + wm * 64 + (lane >> 2);
    int cbase = bn * 128 + wn * 32 + (lane & 3) * 2;
    #pragma unroll
    for (int mf = 0; mf < 4; mf++) {
        #pragma unroll
        for (int half = 0; half < 2; half++) {
            int row = rbase + mf * 16 + half * 8;
            #pragma unroll
            for (int nf = 0; nf < 4; nf++) {
                int col = cbase + nf * 8;
                float ox = acc[mf][nf][half * 2 + 0];
                float oy = acc[mf][nf][half * 2 + 1];
                if (bias) {
                    float2 bb = *(const float2*)(bias + col);
                    ox += bb.x; oy += bb.y;
                }
                if (relu) { ox = fmaxf(ox, 0.f); oy = fmaxf(oy, 0.f); }
                if (resid) {
                    float2 rr = *(const float2*)(resid + (size_t)row * N + col);
                    ox += rr.x; oy += rr.y;
                }
                if (C) {
                    float2 o2; o2.x = ox; o2.y = oy;
                    *(float2*)(C + (size_t)row * N + col) = o2;
                }
                if (Oh)
                    *(__half2*)(Oh + (size_t)row * N + col) = __floats2half2_rn(ox, oy);
            }
        }
    }
}

// ---------------- tensor-core causal flash attention (all 1-term) ------------
// 128 queries/block, 8 warps, 64-key tiles double-buffered.
// QKV packed [row][3072]: Q@0, K@1024, V@2048.
// smem: Q[0,16K); stage s at 16K+s*16K: K@+0, V@+8K.
#define AT_STAGE 16384
#define AT_SMEM  (16384 + 2*AT_STAGE)

__global__ __launch_bounds__(256, 1)
void attn_mma(const __half* __restrict__ QKV, __half* __restrict__ Oh)
{
    extern __shared__ __align__(1024) char smem[];
    const uint32_t sb = smem_u32(smem);
    const int tid = threadIdx.x, wid = tid >> 5, lane = tid & 31;
    const int qt = blockIdx.x, h = blockIdx.y, b = blockIdx.z;
    const int q0 = qt * 128;
    const size_t hoff = (size_t)h * HDIM;

    // Q: 128 rows x 8 chunks
    #pragma unroll
    for (int it = 0; it < 4; it++) {
        int idx = tid + it * 256;
        int r = idx >> 3, c16 = idx & 7;
        uint32_t dst = sb + SWZ128(r * 128 + c16 * 16);
        CP_ASYNC16(dst, QKV + (size_t)(b * TSEQ + q0 + r) * QKVN + hoff + c16 * 8);
    }
    auto load_kv = [&](int s, int kbase) {
        uint32_t base = sb + 16384 + s * AT_STAGE;
        #pragma unroll
        for (int it = 0; it < 4; it++) {
            int idx = tid + it * 256;
            int tl = idx >> 9, r = (idx >> 3) & 63, c16 = idx & 7;
            uint32_t dst = base + tl * 8192 + SWZ128(r * 128 + c16 * 16);
            const __half* src = QKV + (size_t)(b * TSEQ + kbase + r) * QKVN
                                + (tl ? 2048 : 1024) + hoff + c16 * 8;
            CP_ASYNC16(dst, src);
        }
        CP_COMMIT();
    };
    load_kv(0, 0);

    const int a_r  = (lane & 7) + ((lane >> 3) & 1) * 8;
    const int a_cb = (lane >> 4) * 16;
    const int b_l  = lane & 15;
    const int b_r  = b_l & 7;
    const int b_cb = ((b_l >> 3) & 1) * 16;
    const int rA   = q0 + wid * 16 + (lane >> 2);
    const int wrowmax = q0 + wid * 16 + 15;

    float mrow[2] = {-1e30f, -1e30f};
    float lrow[2] = {0.f, 0.f};
    float o[8][4];
    #pragma unroll
    for (int nf = 0; nf < 8; nf++)
        #pragma unroll
        for (int e = 0; e < 4; e++) o[nf][e] = 0.f;
    uint32_t ra[4][4];

    const int nkt = (q0 + 128) / 64;
    for (int kt = 0; kt < nkt; kt++) {
        if (kt + 1 < nkt) { load_kv((kt + 1) & 1, (kt + 1) * 64); CP_WAIT(1); }
        else              { CP_WAIT(0); }
        __syncthreads();
        if (kt == 0) {
            #pragma unroll
            for (int ks = 0; ks < 4; ks++) {
                uint32_t off = SWZ128((wid * 16 + a_r) * 128 + ks * 32 + a_cb);
                ldsm_x4(ra[ks], sb + off);
            }
        }
        if (kt * 64 <= wrowmax) {
            uint32_t kb = sb + 16384 + (kt & 1) * AT_STAGE;
            float s[8][4];
            #pragma unroll
            for (int nf = 0; nf < 8; nf++)
                #pragma unroll
                for (int e = 0; e < 4; e++) s[nf][e] = 0.f;

            #pragma unroll
            for (int ks = 0; ks < 4; ks++) {
                #pragma unroll
                for (int nf = 0; nf < 8; nf++) {
                    uint32_t koff = SWZ128((nf * 8 + b_r) * 128 + ks * 32 + b_cb);
                    uint32_t kbh[2];
                    ldsm_x2(kbh, kb + koff);
                    mma16816(s[nf], ra[ks], kbh);
                }
            }
            #pragma unroll
            for (int nf = 0; nf < 8; nf++) {
                int col = kt * 64 + nf * 8 + (lane & 3) * 2;
                s[nf][0] = (col     > rA)     ? -1e30f : s[nf][0] * 0.125f;
                s[nf][1] = (col + 1 > rA)     ? -1e30f : s[nf][1] * 0.125f;
                s[nf][2] = (col     > rA + 8) ? -1e30f : s[nf][2] * 0.125f;
                s[nf][3] = (col + 1 > rA + 8) ? -1e30f : s[nf][3] * 0.125f;
            }
            float tmA = -1e30f, tmB = -1e30f;
            #pragma unroll
            for (int nf = 0; nf < 8; nf++) {
                tmA = fmaxf(tmA, fmaxf(s[nf][0], s[nf][1]));
                tmB = fmaxf(tmB, fmaxf(s[nf][2], s[nf][3]));
            }
            tmA = fmaxf(tmA, __shfl_xor_sync(0xffffffffu, tmA, 1));
            tmA = fmaxf(tmA, __shfl_xor_sync(0xffffffffu, tmA, 2));
            tmB = fmaxf(tmB, __shfl_xor_sync(0xffffffffu, tmB, 1));
            tmB = fmaxf(tmB, __shfl_xor_sync(0xffffffffu, tmB, 2));
            float mnA = fmaxf(mrow[0], tmA), mnB = fmaxf(mrow[1], tmB);
            float cA = __expf(mrow[0] - mnA), cB = __expf(mrow[1] - mnB);
            float lsA = 0.f, lsB = 0.f;
            #pragma unroll
            for (int nf = 0; nf < 8; nf++) {
                s[nf][0] = __expf(s[nf][0] - mnA);
                s[nf][1] = __expf(s[nf][1] - mnA);
                s[nf][2] = __expf(s[nf][2] - mnB);
                s[nf][3] = __expf(s[nf][3] - mnB);
                lsA += s[nf][0] + s[nf][1];
                lsB += s[nf][2] + s[nf][3];
            }
            lsA += __shfl_xor_sync(0xffffffffu, lsA, 1);
            lsA += __shfl_xor_sync(0xffffffffu, lsA, 2);
            lsB += __shfl_xor_sync(0xffffffffu, lsB, 1);
            lsB += __shfl_xor_sync(0xffffffffu, lsB, 2);
            lrow[0] = lrow[0] * cA + lsA; mrow[0] = mnA;
            lrow[1] = lrow[1] * cB + lsB; mrow[1] = mnB;
            #pragma unroll
            for (int nf = 0; nf < 8; nf++) {
                o[nf][0] *= cA; o[nf][1] *= cA;
                o[nf][2] *= cB; o[nf][3] *= cB;
            }
            #pragma unroll
            for (int ks = 0; ks < 4; ks++) {
                uint32_t phi[4];
                {
                    float* f0 = s[2 * ks];
                    float* f1 = s[2 * ks + 1];
                    phi[0] = packh2(f0[0], f0[1]);
                    phi[1] = packh2(f0[2], f0[3]);
                    phi[2] = packh2(f1[0], f1[1]);
                    phi[3] = packh2(f1[2], f1[3]);
                }
                #pragma unroll
                for (int nf = 0; nf < 8; nf++) {
                    uint32_t voff = SWZ128((ks * 16 + b_l) * 128 + nf * 16);
                    uint32_t vbh[2];
                    ldsm_x2t(vbh, kb + 8192 + voff);
                    mma16816(o[nf], phi, vbh);
                }
            }
        }
        __syncthreads();
    }

    float iA = 1.f / lrow[0], iB = 1.f / lrow[1];
    #pragma unroll
    for (int nf = 0; nf < 8; nf++) {
        int col = nf * 8 + (lane & 3) * 2;
        size_t baseA = (size_t)(b * TSEQ + rA) * EDIM + hoff + col;
        size_t baseB = (size_t)(b * TSEQ + rA + 8) * EDIM + hoff + col;
        *(__half2*)(Oh + baseA) = __floats2half2_rn(o[nf][0] * iA, o[nf][1] * iA);
        *(__half2*)(Oh + baseB) = __floats2half2_rn(o[nf][2] * iB, o[nf][3] * iB);
    }
}

// ---------------- launch -----------------------------------------------------
extern "C" void kernel_launch(void* const* d_in, const int* in_sizes, int n_in,
                              void* d_out, int out_size)
{
    const float* x    = (const float*)d_in[0];
    const float* ln1g = (const float*)d_in[1];
    const float* ln1b = (const float*)d_in[2];
    const float* Wq   = (const float*)d_in[3];
    const float* Wk   = (const float*)d_in[4];
    const float* Wv   = (const float*)d_in[5];
    const float* Wo   = (const float*)d_in[6];
    const float* bo   = (const float*)d_in[7];
    const float* ln2g = (const float*)d_in[8];
    const float* ln2b = (const float*)d_in[9];
    const float* W1   = (const float*)d_in[10];
    const float* b1   = (const float*)d_in[11];
    const float* W2   = (const float*)d_in[12];
    const float* b2   = (const float*)d_in[13];
    float* out = (float*)d_out;

    float* x1;
    __half *ah, *bh, *qkvh, *wqkv, *woh, *w1h, *w2h;
    cudaGetSymbolAddress((void**)&x1,   g_x1);
    cudaGetSymbolAddress((void**)&ah,   g_ah);
    cudaGetSymbolAddress((void**)&bh,   g_bh);
    cudaGetSymbolAddress((void**)&qkvh, g_qkvh);
    cudaGetSymbolAddress((void**)&wqkv, g_wqkv);
    cudaGetSymbolAddress((void**)&woh,  g_woh);
    cudaGetSymbolAddress((void**)&w1h,  g_w1h);
    cudaGetSymbolAddress((void**)&w2h,  g_w2h);

    cudaFuncSetAttribute(gemm_mma, cudaFuncAttributeMaxDynamicSharedMemorySize, G_SMEM);
    cudaFuncSetAttribute(attn_mma, cudaFuncAttributeMaxDynamicSharedMemorySize, AT_SMEM);

    // all weight transposes, one launch
    wtrans_all<<<3072, 256>>>(Wq, Wk, Wv, Wo, W1, W2, wqkv, woh, w1h, w2h);

    // 1. LN1 -> fp16
    ln_kernel<<<MTOK, 256>>>(x, ln1g, ln1b, ah);

    // 2. fused QKV (1-term)
    dim3 gQKV(QKVN/128, MTOK/128);
    gemm_mma<<<gQKV, 256, G_SMEM>>>(ah, wqkv, nullptr, qkvh, nullptr, nullptr, 0, QKVN, EDIM);

    // 3. causal MHA -> fp16
    attn_mma<<<dim3(TSEQ/128, NHEAD, BATCH), 256, AT_SMEM>>>(qkvh, ah);

    // 4. x1 = att @ Wo + bo + x
    dim3 gE(EDIM/128, MTOK/128);
    gemm_mma<<<gE, 256, G_SMEM>>>(ah, woh, x1, nullptr, bo, x, 0, EDIM, EDIM);

    // 5. LN2 -> fp16
    ln_kernel<<<MTOK, 256>>>(x1, ln2g, ln2b, ah);

    // 6. hid = relu(h @ W1 + b1)
    dim3 gF(FDIM/128, MTOK/128);
    gemm_mma<<<gF, 256, G_SMEM>>>(ah, w1h, nullptr, bh, b1, nullptr, 1, FDIM, EDIM);

    // 7. out = hid @ W2 + b2 + x1
    gemm_mma<<<gE, 256, G_SMEM>>>(bh, w2h, out, nullptr, b2, x1, 0, EDIM, FDIM);
}

// round 9
// speedup vs baseline: 13.1344x; 1.0134x over previous
#include <cuda_runtime.h>
#include <cuda_fp16.h>
#include <cstdint>
#include <cstddef>

// Problem dims
#define BATCH 2
#define TSEQ  2048
#define EDIM  1024
#define FDIM  4096
#define NHEAD 16
#define HDIM  64
#define MTOK  (BATCH*TSEQ)   // 4096 rows
#define QKVN  (3*EDIM)       // 3072

// ---------------- scratch (device globals: allocation-free) ----------------
__device__ float  g_x1  [MTOK*EDIM];
__device__ __half g_ah  [MTOK*EDIM];     // ln outputs / attention output
__device__ __half g_bh  [MTOK*FDIM];     // mlp hidden
__device__ __half g_qkvh[MTOK*QKVN];     // fused QKV
__device__ __half g_wqkv[QKVN*EDIM];     // [3072,1024] = Wq^T;Wk^T;Wv^T
__device__ __half g_woh [EDIM*EDIM];
__device__ __half g_w1h [FDIM*EDIM];
__device__ __half g_w2h [EDIM*FDIM];

// ---------------- PTX helpers (sm_80-compatible only) ----------------
__device__ __forceinline__ uint32_t smem_u32(const void* p) {
    uint32_t a;
    asm("{ .reg .u64 t; cvta.to.shared.u64 t, %1; cvt.u32.u64 %0, t; }" : "=r"(a) : "l"(p));
    return a;
}
#define SWZ128(o) ((o) ^ ((((uint32_t)(o)) >> 3) & 0x70u))

#define CP_ASYNC16(dst, src) \
    asm volatile("cp.async.cg.shared.global [%0], [%1], 16;" :: "r"(dst), "l"(src) : "memory")
#define CP_COMMIT()  asm volatile("cp.async.commit_group;" ::: "memory")
#define CP_WAIT(n)   asm volatile("cp.async.wait_group %0;" :: "n"(n) : "memory")

__device__ __forceinline__ void ldsm_x4(uint32_t* r, uint32_t addr) {
    asm volatile("ldmatrix.sync.aligned.m8n8.x4.shared.b16 {%0,%1,%2,%3}, [%4];"
                 : "=r"(r[0]), "=r"(r[1]), "=r"(r[2]), "=r"(r[3]) : "r"(addr));
}
__device__ __forceinline__ void ldsm_x2(uint32_t* r, uint32_t addr) {
    asm volatile("ldmatrix.sync.aligned.m8n8.x2.shared.b16 {%0,%1}, [%2];"
                 : "=r"(r[0]), "=r"(r[1]) : "r"(addr));
}
__device__ __forceinline__ void ldsm_x2t(uint32_t* r, uint32_t addr) {
    asm volatile("ldmatrix.sync.aligned.m8n8.x2.trans.shared.b16 {%0,%1}, [%2];"
                 : "=r"(r[0]), "=r"(r[1]) : "r"(addr));
}
__device__ __forceinline__ void mma16816(float* c, const uint32_t* a, const uint32_t* b) {
    asm volatile("mma.sync.aligned.m16n8k16.row.col.f32.f16.f16.f32 "
                 "{%0,%1,%2,%3}, {%4,%5,%6,%7}, {%8,%9}, {%0,%1,%2,%3};"
                 : "+f"(c[0]), "+f"(c[1]), "+f"(c[2]), "+f"(c[3])
                 : "r"(a[0]), "r"(a[1]), "r"(a[2]), "r"(a[3]),
                   "r"(b[0]), "r"(b[1]));
}
__device__ __forceinline__ uint32_t packh2(float a, float b) {
    __half2 t = __floats2half2_rn(a, b);
    return *(uint32_t*)&t;
}

// ---------------- fused LayerNorm -> fp16 ----------------
__global__ __launch_bounds__(256)
void ln_kernel(const float* __restrict__ x, const float* __restrict__ g,
               const float* __restrict__ b, __half* __restrict__ yh)
{
    __shared__ float red[8];
    int row = blockIdx.x;
    int t = threadIdx.x;
    const float4* xr = (const float4*)(x + (size_t)row * EDIM);
    float4 v = xr[t];
    float s = v.x + v.y + v.z + v.w;
    #pragma unroll
    for (int o = 16; o > 0; o >>= 1) s += __shfl_xor_sync(0xffffffffu, s, o);
    if ((t & 31) == 0) red[t >> 5] = s;
    __syncthreads();
    float tot = 0.f;
    #pragma unroll
    for (int i = 0; i < 8; i++) tot += red[i];
    float mean = tot * (1.0f / EDIM);
    float dx = v.x - mean, dy = v.y - mean, dz = v.z - mean, dw = v.w - mean;
    float s2 = dx*dx + dy*dy + dz*dz + dw*dw;
    __syncthreads();
    #pragma unroll
    for (int o = 16; o > 0; o >>= 1) s2 += __shfl_xor_sync(0xffffffffu, s2, o);
    if ((t & 31) == 0) red[t >> 5] = s2;
    __syncthreads();
    float tot2 = 0.f;
    #pragma unroll
    for (int i = 0; i < 8; i++) tot2 += red[i];
    float r = rsqrtf(tot2 * (1.0f / EDIM) + 1e-5f);
    float4 g4 = ((const float4*)g)[t];
    float4 b4 = ((const float4*)b)[t];
    float o0 = dx * r * g4.x + b4.x;
    float o1 = dy * r * g4.y + b4.y;
    float o2 = dz * r * g4.z + b4.z;
    float o3 = dw * r * g4.w + b4.w;
    size_t base = (size_t)row * EDIM + t * 4;
    *(__half2*)(yh + base)     = __floats2half2_rn(o0, o1);
    *(__half2*)(yh + base + 2) = __floats2half2_rn(o2, o3);
}

// ---------------- batched weight transpose: all 6 weights, one launch --------
__global__ __launch_bounds__(256)
void wtrans_all(const float* __restrict__ Wq, const float* __restrict__ Wk,
                const float* __restrict__ Wv, const float* __restrict__ Wo,
                const float* __restrict__ W1, const float* __restrict__ W2,
                __half* __restrict__ wqkv, __half* __restrict__ woh,
                __half* __restrict__ w1h, __half* __restrict__ w2h)
{
    __shared__ float tile[64][65];
    int bid = blockIdx.x;
    const float* W; __half* T; int K, N, bx, by;
    if (bid < 1024) {
        int seg = bid >> 8, loc = bid & 255;
        W = (seg == 0) ? Wq : (seg == 1) ? Wk : (seg == 2) ? Wv : Wo;
        T = (seg == 0) ? wqkv : (seg == 1) ? wqkv + EDIM*EDIM
          : (seg == 2) ? wqkv + 2*EDIM*EDIM : woh;
        K = EDIM; N = EDIM;
        bx = (loc & 15) * 64; by = (loc >> 4) * 64;
    } else if (bid < 2048) {
        int loc = bid - 1024;
        W = W1; T = w1h; K = EDIM; N = FDIM;
        bx = (loc & 63) * 64; by = (loc >> 6) * 64;
    } else {
        int loc = bid - 2048;
        W = W2; T = w2h; K = FDIM; N = EDIM;
        bx = (loc & 15) * 64; by = (loc >> 4) * 64;
    }
    int tid = threadIdx.x;
    int lr = tid >> 4;
    int lc = (tid & 15) * 4;
    #pragma unroll
    for (int j = 0; j < 64; j += 16) {
        float4 v = *(const float4*)(W + (size_t)(by + lr + j) * N + bx + lc);
        tile[lr + j][lc]     = v.x;
        tile[lr + j][lc + 1] = v.y;
        tile[lr + j][lc + 2] = v.z;
        tile[lr + j][lc + 3] = v.w;
    }
    __syncthreads();
    int sr = tid >> 5;
    int sc = (tid & 31) * 2;
    #pragma unroll
    for (int j = 0; j < 64; j += 8) {
        int n = sr + j;
        __half2 h = __floats2half2_rn(tile[sc][n], tile[sc + 1][n]);
        *(__half2*)(T + (size_t)(bx + n) * K + by + sc) = h;
    }
}

// ---------------- mma.sync fp16 GEMM (1-term, 2 CTAs/SM) ---------------------
#define G_TILE_B 16384
#define G_STAGE_B (2*G_TILE_B)
#define G_SMEM (3*G_STAGE_B)     // 96 KB

__global__ __launch_bounds__(256, 2)
void gemm_mma(const __half* __restrict__ Ah, const __half* __restrict__ Bh,
              float* __restrict__ C, __half* __restrict__ Oh,
              const float* __restrict__ bias,
              const float* __restrict__ resid, int relu, int N, int K)
{
    extern __shared__ __align__(1024) char smem[];
    const uint32_t sb = smem_u32(smem);
    const int tid  = threadIdx.x;
    const int wid  = tid >> 5, lane = tid & 31;
    const int wm   = wid >> 2;
    const int wn   = wid & 3;
    const int bm = blockIdx.y, bn = blockIdx.x;

    const size_t arow0 = (size_t)bm * 128;
    const size_t brow0 = (size_t)bn * 128;

    auto load_stage = [&](int s, int k0) {
        uint32_t base = sb + s * G_STAGE_B;
        #pragma unroll
        for (int it = 0; it < 8; it++) {
            int c   = tid + it * 256;
            int tl  = c >> 10;
            int idx = c & 1023;
            int r   = idx >> 3;
            int c16 = idx & 7;
            uint32_t dst = base + tl * G_TILE_B + SWZ128(r * 128 + c16 * 16);
            const __half* src = tl
                ? Bh + (brow0 + r) * K + k0 + c16 * 8
                : Ah + (arow0 + r) * K + k0 + c16 * 8;
            CP_ASYNC16(dst, src);
        }
        CP_COMMIT();
    };

    float acc[4][4][4];
    #pragma unroll
    for (int mf = 0; mf < 4; mf++)
        #pragma unroll
        for (int nf = 0; nf < 4; nf++)
            #pragma unroll
            for (int e = 0; e < 4; e++) acc[mf][nf][e] = 0.f;

    const int nch = K >> 6;
    load_stage(0, 0);
    load_stage(1, 64);

    const int a_r  = (lane & 7) + ((lane >> 3) & 1) * 8;
    const int a_cb = (lane >> 4) * 16;
    const int b_l  = lane & 15;
    const int b_r  = b_l & 7;
    const int b_cb = ((b_l >> 3) & 1) * 16;

    int s3 = 0;
    for (int i = 0; i < nch; i++) {
        if (i + 2 < nch) {
            int sn = s3 + 2; if (sn >= 3) sn -= 3;
            load_stage(sn, (i + 2) << 6);
            CP_WAIT(2);
        } else if (i + 1 < nch) {
            CP_WAIT(1);
        } else {
            CP_WAIT(0);
        }
        __syncthreads();

        uint32_t tA = sb + s3 * G_STAGE_B;
        uint32_t tB = tA + G_TILE_B;

        #pragma unroll
        for (int ks = 0; ks < 4; ks++) {
            uint32_t ra[4][4], rb[4][2];
            #pragma unroll
            for (int mf = 0; mf < 4; mf++) {
                uint32_t off = SWZ128((wm * 64 + mf * 16 + a_r) * 128 + ks * 32 + a_cb);
                ldsm_x4(ra[mf], tA + off);
            }
            #pragma unroll
            for (int nf = 0; nf < 4; nf++) {
                uint32_t off = SWZ128((wn * 32 + nf * 8 + b_r) * 128 + ks * 32 + b_cb);
                ldsm_x2(rb[nf], tB + off);
            }
            #pragma unroll
            for (int mf = 0; mf < 4; mf++)
                #pragma unroll
                for (int nf = 0; nf < 4; nf++)
                    mma16816(acc[mf][nf], ra[mf], rb[nf]);
        }
        __syncthreads();
        if (++s3 == 3) s3 = 0;
    }

    int rbase = bm * 128 + wm * 64 + (lane >> 2);
    int cbase = bn * 128 + wn * 32 + (lane & 3) * 2;
    #pragma unroll
    for (int mf = 0; mf < 4; mf++) {
        #pragma unroll
        for (int half = 0; half < 2; half++) {
            int row = rbase + mf * 16 + half * 8;
            #pragma unroll
            for (int nf = 0; nf < 4; nf++) {
                int col = cbase + nf * 8;
                float ox = acc[mf][nf][half * 2 + 0];
                float oy = acc[mf][nf][half * 2 + 1];
                if (bias) {
                    float2 bb = *(const float2*)(bias + col);
                    ox += bb.x; oy += bb.y;
                }
                if (relu) { ox = fmaxf(ox, 0.f); oy = fmaxf(oy, 0.f); }
                if (resid) {
                    float2 rr = *(const float2*)(resid + (size_t)row * N + col);
                    ox += rr.x; oy += rr.y;
                }
                if (C) {
                    float2 o2; o2.x = ox; o2.y = oy;
                    *(float2*)(C + (size_t)row * N + col) = o2;
                }
                if (Oh)
                    *(__half2*)(Oh + (size_t)row * N + col) = __floats2half2_rn(ox, oy);
            }
        }
    }
}

// ---------------- tensor-core causal flash attention --------------------------
// 128 queries/block, 8 warps, 64-key tiles double-buffered, 2 CTAs/SM.
// Longest-first: qt = gridDim.x-1-blockIdx.x so heavy blocks start in wave 1.
#define AT_STAGE 16384
#define AT_SMEM  (16384 + 2*AT_STAGE)

__global__ __launch_bounds__(256, 2)
void attn_mma(const __half* __restrict__ QKV, __half* __restrict__ Oh)
{
    extern __shared__ __align__(1024) char smem[];
    const uint32_t sb = smem_u32(smem);
    const int tid = threadIdx.x, wid = tid >> 5, lane = tid & 31;
    const int qt = gridDim.x - 1 - blockIdx.x;
    const int h = blockIdx.y, b = blockIdx.z;
    const int q0 = qt * 128;
    const size_t hoff = (size_t)h * HDIM;

    #pragma unroll
    for (int it = 0; it < 4; it++) {
        int idx = tid + it * 256;
        int r = idx >> 3, c16 = idx & 7;
        uint32_t dst = sb + SWZ128(r * 128 + c16 * 16);
        CP_ASYNC16(dst, QKV + (size_t)(b * TSEQ + q0 + r) * QKVN + hoff + c16 * 8);
    }
    auto load_kv = [&](int s, int kbase) {
        uint32_t base = sb + 16384 + s * AT_STAGE;
        #pragma unroll
        for (int it = 0; it < 4; it++) {
            int idx = tid + it * 256;
            int tl = idx >> 9, r = (idx >> 3) & 63, c16 = idx & 7;
            uint32_t dst = base + tl * 8192 + SWZ128(r * 128 + c16 * 16);
            const __half* src = QKV + (size_t)(b * TSEQ + kbase + r) * QKVN
                                + (tl ? 2048 : 1024) + hoff + c16 * 8;
            CP_ASYNC16(dst, src);
        }
        CP_COMMIT();
    };
    load_kv(0, 0);

    const int a_r  = (lane & 7) + ((lane >> 3) & 1) * 8;
    const int a_cb = (lane >> 4) * 16;
    const int b_l  = lane & 15;
    const int b_r  = b_l & 7;
    const int b_cb = ((b_l >> 3) & 1) * 16;
    const int rA   = q0 + wid * 16 + (lane >> 2);
    const int wrowmax = q0 + wid * 16 + 15;

    float mrow[2] = {-1e30f, -1e30f};
    float lrow[2] = {0.f, 0.f};
    float o[8][4];
    #pragma unroll
    for (int nf = 0; nf < 8; nf++)
        #pragma unroll
        for (int e = 0; e < 4; e++) o[nf][e] = 0.f;
    uint32_t ra[4][4];

    const int nkt = (q0 + 128) / 64;
    for (int kt = 0; kt < nkt; kt++) {
        if (kt + 1 < nkt) { load_kv((kt + 1) & 1, (kt + 1) * 64); CP_WAIT(1); }
        else              { CP_WAIT(0); }
        __syncthreads();
        if (kt == 0) {
            #pragma unroll
            for (int ks = 0; ks < 4; ks++) {
                uint32_t off = SWZ128((wid * 16 + a_r) * 128 + ks * 32 + a_cb);
                ldsm_x4(ra[ks], sb + off);
            }
        }
        if (kt * 64 <= wrowmax) {
            uint32_t kb = sb + 16384 + (kt & 1) * AT_STAGE;
            float s[8][4];
            #pragma unroll
            for (int nf = 0; nf < 8; nf++)
                #pragma unroll
                for (int e = 0; e < 4; e++) s[nf][e] = 0.f;

            #pragma unroll
            for (int ks = 0; ks < 4; ks++) {
                #pragma unroll
                for (int nf = 0; nf < 8; nf++) {
                    uint32_t koff = SWZ128((nf * 8 + b_r) * 128 + ks * 32 + b_cb);
                    uint32_t kbh[2];
                    ldsm_x2(kbh, kb + koff);
                    mma16816(s[nf], ra[ks], kbh);
                }
            }
            #pragma unroll
            for (int nf = 0; nf < 8; nf++) {
                int col = kt * 64 + nf * 8 + (lane & 3) * 2;
                s[nf][0] = (col     > rA)     ? -1e30f : s[nf][0] * 0.125f;
                s[nf][1] = (col + 1 > rA)     ? -1e30f : s[nf][1] * 0.125f;
                s[nf][2] = (col     > rA + 8) ? -1e30f : s[nf][2] * 0.125f;
                s[nf][3] = (col + 1 > rA + 8) ? -1e30f : s[nf][3] * 0.125f;
            }
            float tmA = -1e30f, tmB = -1e30f;
            #pragma unroll
            for (int nf = 0; nf < 8; nf++) {
                tmA = fmaxf(tmA, fmaxf(s[nf][0], s[nf][1]));
                tmB = fmaxf(tmB, fmaxf(s[nf][2], s[nf][3]));
            }
            tmA = fmaxf(tmA, __shfl_xor_sync(0xffffffffu, tmA, 1));
            tmA = fmaxf(tmA, __shfl_xor_sync(0xffffffffu, tmA, 2));
            tmB = fmaxf(tmB, __shfl_xor_sync(0xffffffffu, tmB, 1));
            tmB = fmaxf(tmB, __shfl_xor_sync(0xffffffffu, tmB, 2));
            float mnA = fmaxf(mrow[0], tmA), mnB = fmaxf(mrow[1], tmB);
            float cA = __expf(mrow[0] - mnA), cB = __expf(mrow[1] - mnB);
            float lsA = 0.f, lsB = 0.f;
            #pragma unroll
            for (int nf = 0; nf < 8; nf++) {
                s[nf][0] = __expf(s[nf][0] - mnA);
                s[nf][1] = __expf(s[nf][1] - mnA);
                s[nf][2] = __expf(s[nf][2] - mnB);
                s[nf][3] = __expf(s[nf][3] - mnB);
                lsA += s[nf][0] + s[nf][1];
                lsB += s[nf][2] + s[nf][3];
            }
            lsA += __shfl_xor_sync(0xffffffffu, lsA, 1);
            lsA += __shfl_xor_sync(0xffffffffu, lsA, 2);
            lsB += __shfl_xor_sync(0xffffffffu, lsB, 1);
            lsB += __shfl_xor_sync(0xffffffffu, lsB, 2);
            lrow[0] = lrow[0] * cA + lsA; mrow[0] = mnA;
            lrow[1] = lrow[1] * cB + lsB; mrow[1] = mnB;
            #pragma unroll
            for (int nf = 0; nf < 8; nf++) {
                o[nf][0] *= cA; o[nf][1] *= cA;
                o[nf][2] *= cB; o[nf][3] *= cB;
            }
            #pragma unroll
            for (int ks = 0; ks < 4; ks++) {
                uint32_t phi[4];
                {
                    float* f0 = s[2 * ks];
                    float* f1 = s[2 * ks + 1];
                    phi[0] = packh2(f0[0], f0[1]);
                    phi[1] = packh2(f0[2], f0[3]);
                    phi[2] = packh2(f1[0], f1[1]);
                    phi[3] = packh2(f1[2], f1[3]);
                }
                #pragma unroll
                for (int nf = 0; nf < 8; nf++) {
                    uint32_t voff = SWZ128((ks * 16 + b_l) * 128 + nf * 16);
                    uint32_t vbh[2];
                    ldsm_x2t(vbh, kb + 8192 + voff);
                    mma16816(o[nf], phi, vbh);
                }
            }
        }
        __syncthreads();
    }

    float iA = 1.f / lrow[0], iB = 1.f / lrow[1];
    #pragma unroll
    for (int nf = 0; nf < 8; nf++) {
        int col = nf * 8 + (lane & 3) * 2;
        size_t baseA = (size_t)(b * TSEQ + rA) * EDIM + hoff + col;
        size_t baseB = (size_t)(b * TSEQ + rA + 8) * EDIM + hoff + col;
        *(__half2*)(Oh + baseA) = __floats2half2_rn(o[nf][0] * iA, o[nf][1] * iA);
        *(__half2*)(Oh + baseB) = __floats2half2_rn(o[nf][2] * iB, o[nf][3] * iB);
    }
}

// ---------------- launch -----------------------------------------------------
extern "C" void kernel_launch(void* const* d_in, const int* in_sizes, int n_in,
                              void* d_out, int out_size)
{
    const float* x    = (const float*)d_in[0];
    const float* ln1g = (const float*)d_in[1];
    const float* ln1b = (const float*)d_in[2];
    const float* Wq   = (const float*)d_in[3];
    const float* Wk   = (const float*)d_in[4];
    const float* Wv   = (const float*)d_in[5];
    const float* Wo   = (const float*)d_in[6];
    const float* bo   = (const float*)d_in[7];
    const float* ln2g = (const float*)d_in[8];
    const float* ln2b = (const float*)d_in[9];
    const float* W1   = (const float*)d_in[10];
    const float* b1   = (const float*)d_in[11];
    const float* W2   = (const float*)d_in[12];
    const float* b2   = (const float*)d_in[13];
    float* out = (float*)d_out;

    float* x1;
    __half *ah, *bh, *qkvh, *wqkv, *woh, *w1h, *w2h;
    cudaGetSymbolAddress((void**)&x1,   g_x1);
    cudaGetSymbolAddress((void**)&ah,   g_ah);
    cudaGetSymbolAddress((void**)&bh,   g_bh);
    cudaGetSymbolAddress((void**)&qkvh, g_qkvh);
    cudaGetSymbolAddress((void**)&wqkv, g_wqkv);
    cudaGetSymbolAddress((void**)&woh,  g_woh);
    cudaGetSymbolAddress((void**)&w1h,  g_w1h);
    cudaGetSymbolAddress((void**)&w2h,  g_w2h);

    cudaFuncSetAttribute(gemm_mma, cudaFuncAttributeMaxDynamicSharedMemorySize, G_SMEM);
    cudaFuncSetAttribute(attn_mma, cudaFuncAttributeMaxDynamicSharedMemorySize, AT_SMEM);

    // all weight transposes, one launch
    wtrans_all<<<3072, 256>>>(Wq, Wk, Wv, Wo, W1, W2, wqkv, woh, w1h, w2h);

    // 1. LN1 -> fp16
    ln_kernel<<<MTOK, 256>>>(x, ln1g, ln1b, ah);

    // 2. fused QKV
    dim3 gQKV(QKVN/128, MTOK/128);
    gemm_mma<<<gQKV, 256, G_SMEM>>>(ah, wqkv, nullptr, qkvh, nullptr, nullptr, 0, QKVN, EDIM);

    // 3. causal MHA -> fp16
    attn_mma<<<dim3(TSEQ/128, NHEAD, BATCH), 256, AT_SMEM>>>(qkvh, ah);

    // 4. x1 = att @ Wo + bo + x
    dim3 gE(EDIM/128, MTOK/128);
    gemm_mma<<<gE, 256, G_SMEM>>>(ah, woh, x1, nullptr, bo, x, 0, EDIM, EDIM);

    // 5. LN2 -> fp16
    ln_kernel<<<MTOK, 256>>>(x1, ln2g, ln2b, ah);

    // 6. hid = relu(h @ W1 + b1)
    dim3 gF(FDIM/128, MTOK/128);
    gemm_mma<<<gF, 256, G_SMEM>>>(ah, w1h, nullptr, bh, b1, nullptr, 1, FDIM, EDIM);

    // 7. out = hid @ W2 + b2 + x1
    gemm_mma<<<gE, 256, G_SMEM>>>(bh, w2h, out, nullptr, b2, x1, 0, EDIM, FDIM);
}